// round 1
// baseline (speedup 1.0000x reference)
#include <cuda_runtime.h>

#define CB 4
#define CC 64
#define CH 8
#define CL 2048
#define CO 512   // H*C

typedef unsigned long long ull;

// ---- packed f32x2 helpers (Blackwell FFMA2: 2x fp32 FMA per instruction) ----
__device__ __forceinline__ ull f2pack(float lo, float hi) {
    ull d; asm("mov.b64 %0, {%1, %2};" : "=l"(d) : "f"(lo), "f"(hi)); return d;
}
__device__ __forceinline__ void f2unpack(ull v, float& lo, float& hi) {
    asm("mov.b64 {%0, %1}, %2;" : "=f"(lo), "=f"(hi) : "l"(v));
}
__device__ __forceinline__ ull f2fma(ull a, ull b, ull c) {
    ull d; asm("fma.rn.f32x2 %0, %1, %2, %3;" : "=l"(d) : "l"(a), "l"(b), "l"(c)); return d;
}
__device__ __forceinline__ ull f2mul(ull a, ull b) {
    ull d; asm("mul.rn.f32x2 %0, %1, %2;" : "=l"(d) : "l"(a), "l"(b)); return d;
}

// ---- scratch (device globals: allocation-free rule) ----
__device__ float g_q[CB * CO * CL];
__device__ float g_k[CB * CO * CL];
__device__ float g_v[CB * CO * CL];
__device__ float g_att[CB * CO * CL];

// ============================================================================
// QKV: depthwise conv (k=3, pad=1) + pointwise (512x64) per variant.
// grid (L/64, B, 3 variants), 256 threads.
// ============================================================================
__global__ __launch_bounds__(256) void qkv_kernel(
    const float* __restrict__ x,
    const float* __restrict__ qdw, const float* __restrict__ qdb,
    const float* __restrict__ qpw, const float* __restrict__ qpb,
    const float* __restrict__ kdw, const float* __restrict__ kdb,
    const float* __restrict__ kpw, const float* __restrict__ kpb,
    const float* __restrict__ vdw, const float* __restrict__ vdb,
    const float* __restrict__ vpw, const float* __restrict__ vpb)
{
    __shared__ float ys[CC][68];   // dwconv output tile [c][l], padded
    __shared__ float ws[64][65];   // pointwise weight block [o][c], padded

    int var = blockIdx.z;
    const float* dw = (var == 0) ? qdw : (var == 1) ? kdw : vdw;
    const float* db = (var == 0) ? qdb : (var == 1) ? kdb : vdb;
    const float* pw = (var == 0) ? qpw : (var == 1) ? kpw : vpw;
    const float* pb = (var == 0) ? qpb : (var == 1) ? kpb : vpb;
    float* out     = (var == 0) ? g_q : (var == 1) ? g_k : g_v;
    float scale    = (var == 2) ? 1.0f : 0.35355339059327373f;  // C^-0.25

    int l0 = blockIdx.x * 64;
    int b  = blockIdx.y;
    int tid = threadIdx.x;

    // depthwise conv into ys
    for (int idx = tid; idx < CC * 64; idx += 256) {
        int c = idx >> 6, li = idx & 63;
        int l = l0 + li;
        const float* xr = x + (size_t)(b * CC + c) * CL;
        float w0 = dw[c * 3 + 0], w1 = dw[c * 3 + 1], w2 = dw[c * 3 + 2];
        float xm = (l > 0)      ? xr[l - 1] : 0.f;
        float x0 = xr[l];
        float xp = (l < CL - 1) ? xr[l + 1] : 0.f;
        ys[c][li] = db[c] + w0 * xm + w1 * x0 + w2 * xp;
    }

    int tx = tid & 15, ty = tid >> 4;

    for (int ob = 0; ob < 8; ob++) {
        __syncthreads();   // ys ready (first pass) / prev ws reads done
        for (int idx = tid; idx < 64 * 64; idx += 256) {
            int o = idx >> 6, c = idx & 63;
            ws[o][c] = pw[(size_t)(ob * 64 + o) * CC + c];
        }
        __syncthreads();

        ull acc[4][2];
        #pragma unroll
        for (int i = 0; i < 4; i++) { acc[i][0] = 0ull; acc[i][1] = 0ull; }

        #pragma unroll 4
        for (int c = 0; c < CC; c++) {
            float4 yv = *(const float4*)&ys[c][tx * 4];
            ull y01 = f2pack(yv.x, yv.y), y23 = f2pack(yv.z, yv.w);
            #pragma unroll
            for (int oo = 0; oo < 4; oo++) {
                float w = ws[ty * 4 + oo][c];
                ull ww = f2pack(w, w);
                acc[oo][0] = f2fma(ww, y01, acc[oo][0]);
                acc[oo][1] = f2fma(ww, y23, acc[oo][1]);
            }
        }

        #pragma unroll
        for (int oo = 0; oo < 4; oo++) {
            int o = ob * 64 + ty * 4 + oo;
            float a0, a1, a2, a3;
            f2unpack(acc[oo][0], a0, a1);
            f2unpack(acc[oo][1], a2, a3);
            float bb = pb[o];
            float4 r = make_float4((a0 + bb) * scale, (a1 + bb) * scale,
                                   (a2 + bb) * scale, (a3 + bb) * scale);
            *(float4*)&out[(size_t)(b * CO + o) * CL + l0 + tx * 4] = r;
        }
    }
}

// ============================================================================
// Flash attention: per CTA one (b,h) x 128 queries, key tiles of 64, head dim 64.
// SMEM: Qt[64][128], Kt[64][64], Vs[64][68], Ps[64][132]  = 100352 bytes.
// ============================================================================
#define FLASH_SMEM_FLOATS (64 * 128 + 64 * 64 + 64 * 68 + 64 * 132)
#define FLASH_SMEM_BYTES  (FLASH_SMEM_FLOATS * 4)

__global__ void __launch_bounds__(256, 2) flash_kernel()
{
    extern __shared__ float sm[];
    float* Qt = sm;                          // [c][m]  stride 128
    float* Kt = sm + 64 * 128;               // [c][n]  stride 64
    float* Vs = Kt + 64 * 64;                // [n][d]  stride 68
    float* Ps = Vs + 64 * 68;                // [n][m]  stride 132

    int tid = threadIdx.x;
    int tx = tid & 15, ty = tid >> 4;
    int l0 = blockIdx.x * 128;
    int bh = blockIdx.z * CH + blockIdx.y;   // b*H + h
    const float* qb = g_q + (size_t)bh * CC * CL;
    const float* kb = g_k + (size_t)bh * CC * CL;
    const float* vb = g_v + (size_t)bh * CC * CL;

    // load Q tile (transposed layout already matches global: rows c, cols l)
    for (int i4 = tid; i4 < 64 * 32; i4 += 256) {
        int c = i4 >> 5; int m4 = (i4 & 31) << 2;
        *(float4*)&Qt[c * 128 + m4] = *(const float4*)&qb[(size_t)c * CL + l0 + m4];
    }

    float rmax[8], rsum[8];
    ull o2[8][2];
    #pragma unroll
    for (int i = 0; i < 8; i++) { rmax[i] = -1e30f; rsum[i] = 0.f; o2[i][0] = 0ull; o2[i][1] = 0ull; }

    for (int n0 = 0; n0 < CL; n0 += 64) {
        __syncthreads();   // prior consumers of Kt/Vs/Ps done (and Qt visible, 1st iter)

        // load K tile + transpose V tile
        for (int i4 = tid; i4 < 64 * 16; i4 += 256) {
            int c = i4 >> 4; int n4 = (i4 & 15) << 2;
            *(float4*)&Kt[c * 64 + n4] = *(const float4*)&kb[(size_t)c * CL + n0 + n4];
            float4 vv = *(const float4*)&vb[(size_t)c * CL + n0 + n4];
            Vs[(n4 + 0) * 68 + c] = vv.x;
            Vs[(n4 + 1) * 68 + c] = vv.y;
            Vs[(n4 + 2) * 68 + c] = vv.z;
            Vs[(n4 + 3) * 68 + c] = vv.w;
        }
        __syncthreads();

        // S = Q^T K  (8 m x 4 n per thread, packed over n)
        ull s2[8][2];
        #pragma unroll
        for (int i = 0; i < 8; i++) { s2[i][0] = 0ull; s2[i][1] = 0ull; }

        #pragma unroll 4
        for (int c = 0; c < 64; c++) {
            float4 qa  = *(const float4*)&Qt[c * 128 + ty * 8];
            float4 qb4 = *(const float4*)&Qt[c * 128 + ty * 8 + 4];
            float4 kv  = *(const float4*)&Kt[c * 64 + tx * 4];
            ull k01 = f2pack(kv.x, kv.y), k23 = f2pack(kv.z, kv.w);
            float qs[8] = {qa.x, qa.y, qa.z, qa.w, qb4.x, qb4.y, qb4.z, qb4.w};
            #pragma unroll
            for (int mm = 0; mm < 8; mm++) {
                ull qq = f2pack(qs[mm], qs[mm]);
                s2[mm][0] = f2fma(qq, k01, s2[mm][0]);
                s2[mm][1] = f2fma(qq, k23, s2[mm][1]);
            }
        }

        // online softmax + P store, in two halves (keeps register pressure down)
        #pragma unroll
        for (int half = 0; half < 2; half++) {
            float pf[4][4];
            #pragma unroll
            for (int mm2 = 0; mm2 < 4; mm2++) {
                int mm = half * 4 + mm2;
                float s0, s1, sA, sB;
                f2unpack(s2[mm][0], s0, s1);
                f2unpack(s2[mm][1], sA, sB);
                float mx = fmaxf(fmaxf(s0, s1), fmaxf(sA, sB));
                #pragma unroll
                for (int off = 8; off; off >>= 1)
                    mx = fmaxf(mx, __shfl_xor_sync(0xffffffffu, mx, off));
                float nm = fmaxf(rmax[mm], mx);
                float corr = __expf(rmax[mm] - nm);
                float p0 = __expf(s0 - nm), p1 = __expf(s1 - nm);
                float p2 = __expf(sA - nm), p3 = __expf(sB - nm);
                float ps = p0 + p1 + p2 + p3;
                #pragma unroll
                for (int off = 8; off; off >>= 1)
                    ps += __shfl_xor_sync(0xffffffffu, ps, off);
                rsum[mm] = rsum[mm] * corr + ps;
                rmax[mm] = nm;
                ull cc2 = f2pack(corr, corr);
                o2[mm][0] = f2mul(o2[mm][0], cc2);
                o2[mm][1] = f2mul(o2[mm][1], cc2);
                pf[mm2][0] = p0; pf[mm2][1] = p1; pf[mm2][2] = p2; pf[mm2][3] = p3;
            }
            #pragma unroll
            for (int nn = 0; nn < 4; nn++) {
                float4 r = make_float4(pf[0][nn], pf[1][nn], pf[2][nn], pf[3][nn]);
                *(float4*)&Ps[(tx * 4 + nn) * 132 + ty * 8 + half * 4] = r;
            }
        }
        __syncthreads();

        // O += P V  (8 m x 4 d per thread, packed over d)
        #pragma unroll 4
        for (int n = 0; n < 64; n++) {
            float4 pa  = *(const float4*)&Ps[n * 132 + ty * 8];
            float4 pb4 = *(const float4*)&Ps[n * 132 + ty * 8 + 4];
            float4 vv  = *(const float4*)&Vs[n * 68 + tx * 4];
            ull v01 = f2pack(vv.x, vv.y), v23 = f2pack(vv.z, vv.w);
            float pv[8] = {pa.x, pa.y, pa.z, pa.w, pb4.x, pb4.y, pb4.z, pb4.w};
            #pragma unroll
            for (int mm = 0; mm < 8; mm++) {
                ull pp = f2pack(pv[mm], pv[mm]);
                o2[mm][0] = f2fma(pp, v01, o2[mm][0]);
                o2[mm][1] = f2fma(pp, v23, o2[mm][1]);
            }
        }
    }

    __syncthreads();
    // stage normalized O into Qt as [d][m] for coalesced writeback
    #pragma unroll
    for (int mm = 0; mm < 8; mm++) {
        float inv = 1.0f / rsum[mm];
        float a0, a1, a2, a3;
        f2unpack(o2[mm][0], a0, a1);
        f2unpack(o2[mm][1], a2, a3);
        int m = ty * 8 + mm;
        Qt[(tx * 4 + 0) * 128 + m] = a0 * inv;
        Qt[(tx * 4 + 1) * 128 + m] = a1 * inv;
        Qt[(tx * 4 + 2) * 128 + m] = a2 * inv;
        Qt[(tx * 4 + 3) * 128 + m] = a3 * inv;
    }
    __syncthreads();
    float* ob = g_att + (size_t)bh * CC * CL;
    for (int i4 = tid; i4 < 64 * 32; i4 += 256) {
        int d = i4 >> 5; int m4 = (i4 & 31) << 2;
        *(float4*)&ob[(size_t)d * CL + l0 + m4] = *(const float4*)&Qt[d * 128 + m4];
    }
}

// ============================================================================
// Unify heads: y[b,c,l] = sum_o att[b,o,l] * u_w[c,o] + u_b[c].
// grid (L/128, B), 256 threads = (32 tx x 8 ty), 8c x 4l per thread.
// ============================================================================
__global__ __launch_bounds__(256) void unify_kernel(
    const float* __restrict__ uw, const float* __restrict__ ub,
    float* __restrict__ y)
{
    __shared__ float as_[64][128];
    __shared__ float ws[64][65];
    int tid = threadIdx.x;
    int tx = tid & 31, ty = tid >> 5;
    int l0 = blockIdx.x * 128, b = blockIdx.y;

    ull acc[8][2];
    #pragma unroll
    for (int i = 0; i < 8; i++) { acc[i][0] = 0ull; acc[i][1] = 0ull; }

    for (int oc = 0; oc < 8; oc++) {
        __syncthreads();
        for (int i4 = tid; i4 < 64 * 32; i4 += 256) {
            int o = i4 >> 5; int l4 = (i4 & 31) << 2;
            *(float4*)&as_[o][l4] =
                *(const float4*)&g_att[(size_t)(b * CO + oc * 64 + o) * CL + l0 + l4];
        }
        for (int idx = tid; idx < 64 * 64; idx += 256) {
            int c = idx >> 6, o = idx & 63;
            ws[c][o] = uw[(size_t)c * CO + oc * 64 + o];
        }
        __syncthreads();

        #pragma unroll 4
        for (int o = 0; o < 64; o++) {
            float4 av = *(const float4*)&as_[o][tx * 4];
            ull a01 = f2pack(av.x, av.y), a23 = f2pack(av.z, av.w);
            #pragma unroll
            for (int cc = 0; cc < 8; cc++) {
                float w = ws[ty * 8 + cc][o];
                ull ww = f2pack(w, w);
                acc[cc][0] = f2fma(ww, a01, acc[cc][0]);
                acc[cc][1] = f2fma(ww, a23, acc[cc][1]);
            }
        }
    }

    #pragma unroll
    for (int cc = 0; cc < 8; cc++) {
        int c = ty * 8 + cc;
        float bb = ub[c];
        float a0, a1, a2, a3;
        f2unpack(acc[cc][0], a0, a1);
        f2unpack(acc[cc][1], a2, a3);
        float4 r = make_float4(a0 + bb, a1 + bb, a2 + bb, a3 + bb);
        *(float4*)&y[(size_t)(b * CC + c) * CL + l0 + tx * 4] = r;
    }
}

// ============================================================================
extern "C" void kernel_launch(void* const* d_in, const int* in_sizes, int n_in,
                              void* d_out, int out_size)
{
    (void)in_sizes; (void)n_in; (void)out_size;
    const float* x    = (const float*)d_in[0];
    const float* q_dw = (const float*)d_in[1];
    const float* q_db = (const float*)d_in[2];
    const float* q_pw = (const float*)d_in[3];
    const float* q_pb = (const float*)d_in[4];
    const float* k_dw = (const float*)d_in[5];
    const float* k_db = (const float*)d_in[6];
    const float* k_pw = (const float*)d_in[7];
    const float* k_pb = (const float*)d_in[8];
    const float* v_dw = (const float*)d_in[9];
    const float* v_db = (const float*)d_in[10];
    const float* v_pw = (const float*)d_in[11];
    const float* v_pb = (const float*)d_in[12];
    const float* u_w  = (const float*)d_in[13];
    const float* u_b  = (const float*)d_in[14];

    cudaFuncSetAttribute(flash_kernel,
                         cudaFuncAttributeMaxDynamicSharedMemorySize,
                         FLASH_SMEM_BYTES);

    qkv_kernel<<<dim3(CL / 64, CB, 3), 256>>>(
        x, q_dw, q_db, q_pw, q_pb, k_dw, k_db, k_pw, k_pb, v_dw, v_db, v_pw, v_pb);

    flash_kernel<<<dim3(CL / 128, CH, CB), 256, FLASH_SMEM_BYTES>>>();

    unify_kernel<<<dim3(CL / 128, CB), 256>>>(u_w, u_b, (float*)d_out);
}

// round 3
// speedup vs baseline: 4.5239x; 4.5239x over previous
#include <cuda_runtime.h>
#include <cuda_bf16.h>
#include <cstdint>

#define CB 4
#define CC 64
#define CH 8
#define CL 2048
#define CO 512

typedef unsigned long long ull;

// ---------------- packed f32x2 helpers ----------------
__device__ __forceinline__ ull f2pack(float lo, float hi) {
    ull d; asm("mov.b64 %0, {%1, %2};" : "=l"(d) : "f"(lo), "f"(hi)); return d;
}
__device__ __forceinline__ void f2unpack(ull v, float& lo, float& hi) {
    asm("mov.b64 {%0, %1}, %2;" : "=f"(lo), "=f"(hi) : "l"(v));
}
__device__ __forceinline__ ull f2fma(ull a, ull b, ull c) {
    ull d; asm("fma.rn.f32x2 %0, %1, %2, %3;" : "=l"(d) : "l"(a), "l"(b), "l"(c)); return d;
}

// ---------------- cp.async ----------------
__device__ __forceinline__ void cpa16(uint32_t s, const void* g) {
    asm volatile("cp.async.cg.shared.global [%0], [%1], 16;" :: "r"(s), "l"(g));
}
#define CP_COMMIT() asm volatile("cp.async.commit_group;" ::: "memory")
#define CP_WAIT(n)  asm volatile("cp.async.wait_group %0;" :: "n"(n) : "memory")

__device__ __forceinline__ uint32_t smem_u32(const void* p) {
    uint32_t a;
    asm("{ .reg .u64 t; cvta.to.shared.u64 t, %1; cvt.u32.u64 %0, t; }" : "=r"(a) : "l"(p));
    return a;
}

// ---------------- HMMA m16n8k16 bf16 (family-portable PTX) ----------------
__device__ __forceinline__ void hmma(float* c,
                                     uint32_t a0, uint32_t a1, uint32_t a2, uint32_t a3,
                                     uint32_t b0, uint32_t b1) {
    asm volatile(
        "mma.sync.aligned.m16n8k16.row.col.f32.bf16.bf16.f32 "
        "{%0,%1,%2,%3},{%4,%5,%6,%7},{%8,%9},{%0,%1,%2,%3};"
        : "+f"(c[0]), "+f"(c[1]), "+f"(c[2]), "+f"(c[3])
        : "r"(a0), "r"(a1), "r"(a2), "r"(a3), "r"(b0), "r"(b1));
}

// ---------------- scratch ----------------
__device__ __nv_bfloat16 g_qt[CB * CH * CL * CC];  // [bh][l][c]
__device__ __nv_bfloat16 g_kt[CB * CH * CL * CC];  // [bh][l][c]
__device__ __nv_bfloat16 g_vv[CB * CH * CC * CL];  // [bh][c(d)][l]
__device__ float g_att[CB * CO * CL];              // [(b*512 + h*64 + d)][l]

// ============================================================================
// QKV: dwconv + pointwise, emits bf16 in MMA layouts.
// ============================================================================
__global__ __launch_bounds__(256) void qkv_kernel(
    const float* __restrict__ x,
    const float* __restrict__ qdw, const float* __restrict__ qdb,
    const float* __restrict__ qpw, const float* __restrict__ qpb,
    const float* __restrict__ kdw, const float* __restrict__ kdb,
    const float* __restrict__ kpw, const float* __restrict__ kpb,
    const float* __restrict__ vdw, const float* __restrict__ vdb,
    const float* __restrict__ vpw, const float* __restrict__ vpb)
{
    __shared__ float ys[CC][68];
    __shared__ float ws[64][65];
    __shared__ __nv_bfloat16 stb[64][72];

    int var = blockIdx.z;
    const float* dw = (var == 0) ? qdw : (var == 1) ? kdw : vdw;
    const float* db = (var == 0) ? qdb : (var == 1) ? kdb : vdb;
    const float* pw = (var == 0) ? qpw : (var == 1) ? kpw : vpw;
    const float* pb = (var == 0) ? qpb : (var == 1) ? kpb : vpb;
    float scale    = (var == 2) ? 1.0f : 0.35355339059327373f;

    int l0 = blockIdx.x * 64;
    int b  = blockIdx.y;
    int tid = threadIdx.x;

    for (int idx = tid; idx < CC * 64; idx += 256) {
        int c = idx >> 6, li = idx & 63;
        int l = l0 + li;
        const float* xr = x + (size_t)(b * CC + c) * CL;
        float w0 = dw[c * 3 + 0], w1 = dw[c * 3 + 1], w2 = dw[c * 3 + 2];
        float xm = (l > 0)      ? xr[l - 1] : 0.f;
        float x0 = xr[l];
        float xp = (l < CL - 1) ? xr[l + 1] : 0.f;
        ys[c][li] = db[c] + w0 * xm + w1 * x0 + w2 * xp;
    }

    int tx = tid & 15, ty = tid >> 4;

    for (int ob = 0; ob < 8; ob++) {   // ob == head index
        __syncthreads();
        for (int idx = tid; idx < 64 * 64; idx += 256) {
            int o = idx >> 6, c = idx & 63;
            ws[o][c] = pw[(size_t)(ob * 64 + o) * CC + c];
        }
        __syncthreads();

        ull acc[4][2];
        #pragma unroll
        for (int i = 0; i < 4; i++) { acc[i][0] = 0ull; acc[i][1] = 0ull; }

        #pragma unroll 4
        for (int c = 0; c < CC; c++) {
            float4 yv = *(const float4*)&ys[c][tx * 4];
            ull y01 = f2pack(yv.x, yv.y), y23 = f2pack(yv.z, yv.w);
            #pragma unroll
            for (int oo = 0; oo < 4; oo++) {
                float w = ws[ty * 4 + oo][c];
                ull ww = f2pack(w, w);
                acc[oo][0] = f2fma(ww, y01, acc[oo][0]);
                acc[oo][1] = f2fma(ww, y23, acc[oo][1]);
            }
        }

        float vals[4][4];   // [oo(c)][li(l)]
        #pragma unroll
        for (int oo = 0; oo < 4; oo++) {
            float bb = pb[ob * 64 + ty * 4 + oo];
            float a0, a1, a2, a3;
            f2unpack(acc[oo][0], a0, a1);
            f2unpack(acc[oo][1], a2, a3);
            vals[oo][0] = (a0 + bb) * scale; vals[oo][1] = (a1 + bb) * scale;
            vals[oo][2] = (a2 + bb) * scale; vals[oo][3] = (a3 + bb) * scale;
        }

        int bh = b * CH + ob;
        if (var == 2) {
            // v: [bh][c][l]
            #pragma unroll
            for (int oo = 0; oo < 4; oo++) {
                __nv_bfloat162 h0 = __floats2bfloat162_rn(vals[oo][0], vals[oo][1]);
                __nv_bfloat162 h1 = __floats2bfloat162_rn(vals[oo][2], vals[oo][3]);
                uint2 pk = make_uint2(*(uint32_t*)&h0, *(uint32_t*)&h1);
                *(uint2*)&g_vv[((size_t)(bh * CC) + ty * 4 + oo) * CL + l0 + tx * 4] = pk;
            }
        } else {
            // q/k: transpose to [bh][l][c] via smem
            #pragma unroll
            for (int li = 0; li < 4; li++) {
                __nv_bfloat162 h0 = __floats2bfloat162_rn(vals[0][li], vals[1][li]);
                __nv_bfloat162 h1 = __floats2bfloat162_rn(vals[2][li], vals[3][li]);
                uint2 pk = make_uint2(*(uint32_t*)&h0, *(uint32_t*)&h1);
                *(uint2*)&stb[tx * 4 + li][ty * 4] = pk;
            }
            __syncthreads();
            __nv_bfloat16* outp = (var == 0) ? g_qt : g_kt;
            for (int c2 = tid; c2 < 512; c2 += 256) {
                int l = c2 >> 3, j = c2 & 7;
                *(uint4*)&outp[((size_t)bh * CL + l0 + l) * CC + j * 8] =
                    *(const uint4*)&stb[l][j * 8];
            }
        }
    }
}

// ============================================================================
// Flash attention on HMMA (mma.sync m16n8k16 bf16).
// CTA: 128 queries, 4 warps x 32 query rows. Key tiles of 64, 32 iterations.
// No max-subtraction (|S| << 1): P = exp(S); O fp32 accumulators in registers.
// SMEM layout (bytes):
//   [0, 33792)      : Qsm (128 x 72 bf16, first 18432B) -> later Osm (64 x 132 f32)
//   [33792, 43008)  : K buf 0   (64 keys x 72 c bf16)
//   [43008, 52224)  : K buf 1
//   [52224, 61440)  : V buf 0   (64 d x 72 key bf16)
//   [61440, 70656)  : V buf 1
// ============================================================================
#define KT      64
#define NT      (CL / KT)
#define QSM_OFF 0
#define OSM_OFF 0
#define K_OFF0  33792
#define K_OFF1  43008
#define V_OFF0  52224
#define V_OFF1  61440
#define FL_SMEM 70656

__global__ void __launch_bounds__(128, 2) flash_kernel()
{
    extern __shared__ char sm[];
    uint32_t sb = smem_u32(sm);
    __nv_bfloat16* Qsm = (__nv_bfloat16*)(sm + QSM_OFF);
    float* Osm = (float*)(sm + OSM_OFF);

    int tid = threadIdx.x;
    int w   = tid >> 5;
    int ln  = tid & 31;
    int gp  = ln >> 2;          // groupID (row within 8)
    int tg  = ln & 3;           // thread in group
    int l0  = blockIdx.x * 128;
    int bh  = blockIdx.z * CH + blockIdx.y;

    const __nv_bfloat16* qg = g_qt + (size_t)bh * CL * CC;
    const __nv_bfloat16* kg = g_kt + (size_t)bh * CL * CC;
    const __nv_bfloat16* vg = g_vv + (size_t)bh * CC * CL;

    const uint32_t koff[2] = {K_OFF0, K_OFF1};
    const uint32_t voff[2] = {V_OFF0, V_OFF1};

    // ---- load Q tile into smem (128 rows x 64 c, stride 72) ----
    for (int c = tid; c < 1024; c += 128) {
        int r = c >> 3, j = c & 7;
        cpa16(sb + QSM_OFF + r * 144 + j * 16, qg + ((size_t)(l0 + r)) * CC + j * 8);
    }
    CP_COMMIT();
    // ---- preload K/V tile 0 ----
    for (int c = tid; c < 512; c += 128) {
        int r = c >> 3, j = c & 7;
        cpa16(sb + K_OFF0 + r * 144 + j * 16, kg + ((size_t)r) * CC + j * 8);
        cpa16(sb + V_OFF0 + r * 144 + j * 16, vg + (size_t)r * CL + j * 8);
    }
    CP_COMMIT();

    // ---- extract Q fragments (kept in registers for the whole key loop) ----
    CP_WAIT(1);
    __syncthreads();
    uint32_t qa[2][4][4];
    #pragma unroll
    for (int mt = 0; mt < 2; mt++) {
        int row = w * 32 + mt * 16 + gp;
        #pragma unroll
        for (int ks = 0; ks < 4; ks++) {
            int col = ks * 16 + tg * 2;
            qa[mt][ks][0] = *(const uint32_t*)&Qsm[(row)     * 72 + col];
            qa[mt][ks][1] = *(const uint32_t*)&Qsm[(row + 8) * 72 + col];
            qa[mt][ks][2] = *(const uint32_t*)&Qsm[(row)     * 72 + col + 8];
            qa[mt][ks][3] = *(const uint32_t*)&Qsm[(row + 8) * 72 + col + 8];
        }
    }
    __syncthreads();   // everyone has Q frags; Qsm region is now dead

    float Oacc[2][8][4];
    #pragma unroll
    for (int mt = 0; mt < 2; mt++)
        #pragma unroll
        for (int n = 0; n < 8; n++)
            #pragma unroll
            for (int r = 0; r < 4; r++) Oacc[mt][n][r] = 0.f;
    float rs[2][2] = {{0.f, 0.f}, {0.f, 0.f}};

    for (int i = 0; i < NT; i++) {
        int buf = i & 1;
        // prefetch tile i+1 into buf^1 (freed by end-of-iteration sync of i-1)
        if (i + 1 < NT) {
            int n0 = (i + 1) * KT;
            uint32_t kd = koff[buf ^ 1], vd = voff[buf ^ 1];
            for (int c = tid; c < 512; c += 128) {
                int r = c >> 3, j = c & 7;
                cpa16(sb + kd + r * 144 + j * 16, kg + ((size_t)(n0 + r)) * CC + j * 8);
                cpa16(sb + vd + r * 144 + j * 16, vg + (size_t)r * CL + n0 + j * 8);
            }
            CP_COMMIT();
            CP_WAIT(1);
        } else {
            CP_WAIT(0);
        }
        __syncthreads();

        const __nv_bfloat16* Ks = (const __nv_bfloat16*)(sm + koff[buf]);
        const __nv_bfloat16* Vs = (const __nv_bfloat16*)(sm + voff[buf]);

        // ---- MMA1: S = Q . K^T  (per warp: 32 q x 64 keys) ----
        float Sacc[2][8][4];
        #pragma unroll
        for (int mt = 0; mt < 2; mt++)
            #pragma unroll
            for (int n = 0; n < 8; n++)
                #pragma unroll
                for (int r = 0; r < 4; r++) Sacc[mt][n][r] = 0.f;

        #pragma unroll
        for (int ks = 0; ks < 4; ks++) {
            #pragma unroll
            for (int n = 0; n < 8; n++) {
                int krow = n * 8 + gp;
                int kcol = ks * 16 + tg * 2;
                uint32_t b0 = *(const uint32_t*)&Ks[krow * 72 + kcol];
                uint32_t b1 = *(const uint32_t*)&Ks[krow * 72 + kcol + 8];
                hmma(Sacc[0][n], qa[0][ks][0], qa[0][ks][1], qa[0][ks][2], qa[0][ks][3], b0, b1);
                hmma(Sacc[1][n], qa[1][ks][0], qa[1][ks][1], qa[1][ks][2], qa[1][ks][3], b0, b1);
            }
        }

        // ---- softmax (P = exp(S)) fused with MMA2: O += P . V ----
        #pragma unroll
        for (int ks = 0; ks < 4; ks++) {
            uint32_t vb[8][2];
            #pragma unroll
            for (int n = 0; n < 8; n++) {
                int vrow = n * 8 + gp;          // d index
                int vcol = ks * 16 + tg * 2;    // key index
                vb[n][0] = *(const uint32_t*)&Vs[vrow * 72 + vcol];
                vb[n][1] = *(const uint32_t*)&Vs[vrow * 72 + vcol + 8];
            }
            #pragma unroll
            for (int mt = 0; mt < 2; mt++) {
                float e0 = __expf(Sacc[mt][2 * ks][0]);
                float e1 = __expf(Sacc[mt][2 * ks][1]);
                float e2 = __expf(Sacc[mt][2 * ks][2]);
                float e3 = __expf(Sacc[mt][2 * ks][3]);
                float f0 = __expf(Sacc[mt][2 * ks + 1][0]);
                float f1 = __expf(Sacc[mt][2 * ks + 1][1]);
                float f2 = __expf(Sacc[mt][2 * ks + 1][2]);
                float f3 = __expf(Sacc[mt][2 * ks + 1][3]);
                rs[mt][0] += (e0 + e1) + (f0 + f1);
                rs[mt][1] += (e2 + e3) + (f2 + f3);
                __nv_bfloat162 p0 = __floats2bfloat162_rn(e0, e1);
                __nv_bfloat162 p1 = __floats2bfloat162_rn(e2, e3);
                __nv_bfloat162 p2 = __floats2bfloat162_rn(f0, f1);
                __nv_bfloat162 p3 = __floats2bfloat162_rn(f2, f3);
                uint32_t pa0 = *(uint32_t*)&p0, pa1 = *(uint32_t*)&p1;
                uint32_t pa2 = *(uint32_t*)&p2, pa3 = *(uint32_t*)&p3;
                #pragma unroll
                for (int n = 0; n < 8; n++)
                    hmma(Oacc[mt][n], pa0, pa1, pa2, pa3, vb[n][0], vb[n][1]);
            }
        }
        __syncthreads();   // all reads of buf done before next iter overwrites it
    }

    // ---- finalize: row-sum reduce across the 4 lanes of each row group ----
    #pragma unroll
    for (int mt = 0; mt < 2; mt++) {
        #pragma unroll
        for (int h = 0; h < 2; h++) {
            float v = rs[mt][h];
            v += __shfl_xor_sync(0xffffffffu, v, 1);
            v += __shfl_xor_sync(0xffffffffu, v, 2);
            rs[mt][h] = 1.0f / v;
        }
    }

    // ---- stage O (normalized) into Osm[d][q], then coalesced global store ----
    #pragma unroll
    for (int mt = 0; mt < 2; mt++) {
        int qb = w * 32 + mt * 16 + gp;
        #pragma unroll
        for (int n = 0; n < 8; n++) {
            int d = n * 8 + tg * 2;
            Osm[(d)     * 132 + qb]     = Oacc[mt][n][0] * rs[mt][0];
            Osm[(d + 1) * 132 + qb]     = Oacc[mt][n][1] * rs[mt][0];
            Osm[(d)     * 132 + qb + 8] = Oacc[mt][n][2] * rs[mt][1];
            Osm[(d + 1) * 132 + qb + 8] = Oacc[mt][n][3] * rs[mt][1];
        }
    }
    __syncthreads();

    float* ob = g_att + (size_t)bh * CC * CL + l0;
    for (int c = tid; c < 64 * 32; c += 128) {
        int d = c >> 5, q4 = (c & 31) << 2;
        *(float4*)&ob[(size_t)d * CL + q4] = *(const float4*)&Osm[d * 132 + q4];
    }
}

// ============================================================================
// Unify heads (fp32 att): y[b,c,l] = sum_o att[b,o,l] * u_w[c,o] + u_b[c]
// ============================================================================
__global__ __launch_bounds__(256) void unify_kernel(
    const float* __restrict__ uw, const float* __restrict__ ub,
    float* __restrict__ y)
{
    __shared__ float as_[64][128];
    __shared__ float ws[64][65];
    int tid = threadIdx.x;
    int tx = tid & 31, ty = tid >> 5;
    int l0 = blockIdx.x * 128, b = blockIdx.y;

    ull acc[8][2];
    #pragma unroll
    for (int i = 0; i < 8; i++) { acc[i][0] = 0ull; acc[i][1] = 0ull; }

    for (int oc = 0; oc < 8; oc++) {
        __syncthreads();
        for (int i4 = tid; i4 < 64 * 32; i4 += 256) {
            int o = i4 >> 5; int l4 = (i4 & 31) << 2;
            *(float4*)&as_[o][l4] =
                *(const float4*)&g_att[(size_t)(b * CO + oc * 64 + o) * CL + l0 + l4];
        }
        for (int idx = tid; idx < 64 * 64; idx += 256) {
            int c = idx >> 6, o = idx & 63;
            ws[c][o] = uw[(size_t)c * CO + oc * 64 + o];
        }
        __syncthreads();

        #pragma unroll 4
        for (int o = 0; o < 64; o++) {
            float4 av = *(const float4*)&as_[o][tx * 4];
            ull a01 = f2pack(av.x, av.y), a23 = f2pack(av.z, av.w);
            #pragma unroll
            for (int cc = 0; cc < 8; cc++) {
                float w = ws[ty * 8 + cc][o];
                ull ww = f2pack(w, w);
                acc[cc][0] = f2fma(ww, a01, acc[cc][0]);
                acc[cc][1] = f2fma(ww, a23, acc[cc][1]);
            }
        }
    }

    #pragma unroll
    for (int cc = 0; cc < 8; cc++) {
        int c = ty * 8 + cc;
        float bb = ub[c];
        float a0, a1, a2, a3;
        f2unpack(acc[cc][0], a0, a1);
        f2unpack(acc[cc][1], a2, a3);
        float4 r = make_float4(a0 + bb, a1 + bb, a2 + bb, a3 + bb);
        *(float4*)&y[(size_t)(b * CC + c) * CL + l0 + tx * 4] = r;
    }
}

// ============================================================================
extern "C" void kernel_launch(void* const* d_in, const int* in_sizes, int n_in,
                              void* d_out, int out_size)
{
    (void)in_sizes; (void)n_in; (void)out_size;
    const float* x    = (const float*)d_in[0];
    const float* q_dw = (const float*)d_in[1];
    const float* q_db = (const float*)d_in[2];
    const float* q_pw = (const float*)d_in[3];
    const float* q_pb = (const float*)d_in[4];
    const float* k_dw = (const float*)d_in[5];
    const float* k_db = (const float*)d_in[6];
    const float* k_pw = (const float*)d_in[7];
    const float* k_pb = (const float*)d_in[8];
    const float* v_dw = (const float*)d_in[9];
    const float* v_db = (const float*)d_in[10];
    const float* v_pw = (const float*)d_in[11];
    const float* v_pb = (const float*)d_in[12];
    const float* u_w  = (const float*)d_in[13];
    const float* u_b  = (const float*)d_in[14];

    cudaFuncSetAttribute(flash_kernel,
                         cudaFuncAttributeMaxDynamicSharedMemorySize, FL_SMEM);

    qkv_kernel<<<dim3(CL / 64, CB, 3), 256>>>(
        x, q_dw, q_db, q_pw, q_pb, k_dw, k_db, k_pw, k_pb, v_dw, v_db, v_pw, v_pb);

    flash_kernel<<<dim3(CL / 128, CH, CB), 128, FL_SMEM>>>();

    unify_kernel<<<dim3(CL / 128, CB), 256>>>(u_w, u_b, (float*)d_out);
}

// round 4
// speedup vs baseline: 5.8995x; 1.3041x over previous
#include <cuda_runtime.h>
#include <cuda_bf16.h>
#include <cstdint>

#define CB 4
#define CC 64
#define CH 8
#define CL 2048
#define CO 512

typedef unsigned long long ull;

// ---------------- packed f32x2 helpers ----------------
__device__ __forceinline__ ull f2pack(float lo, float hi) {
    ull d; asm("mov.b64 %0, {%1, %2};" : "=l"(d) : "f"(lo), "f"(hi)); return d;
}
__device__ __forceinline__ void f2unpack(ull v, float& lo, float& hi) {
    asm("mov.b64 {%0, %1}, %2;" : "=f"(lo), "=f"(hi) : "l"(v));
}
__device__ __forceinline__ ull f2fma(ull a, ull b, ull c) {
    ull d; asm("fma.rn.f32x2 %0, %1, %2, %3;" : "=l"(d) : "l"(a), "l"(b), "l"(c)); return d;
}

// ---------------- cp.async ----------------
__device__ __forceinline__ void cpa16(uint32_t s, const void* g) {
    asm volatile("cp.async.cg.shared.global [%0], [%1], 16;" :: "r"(s), "l"(g));
}
#define CP_COMMIT() asm volatile("cp.async.commit_group;" ::: "memory")
#define CP_WAIT(n)  asm volatile("cp.async.wait_group %0;" :: "n"(n) : "memory")

__device__ __forceinline__ uint32_t smem_u32(const void* p) {
    uint32_t a;
    asm("{ .reg .u64 t; cvta.to.shared.u64 t, %1; cvt.u32.u64 %0, t; }" : "=r"(a) : "l"(p));
    return a;
}

// ---------------- HMMA m16n8k16 bf16 ----------------
__device__ __forceinline__ void hmma(float* c,
                                     uint32_t a0, uint32_t a1, uint32_t a2, uint32_t a3,
                                     uint32_t b0, uint32_t b1) {
    asm volatile(
        "mma.sync.aligned.m16n8k16.row.col.f32.bf16.bf16.f32 "
        "{%0,%1,%2,%3},{%4,%5,%6,%7},{%8,%9},{%0,%1,%2,%3};"
        : "+f"(c[0]), "+f"(c[1]), "+f"(c[2]), "+f"(c[3])
        : "r"(a0), "r"(a1), "r"(a2), "r"(a3), "r"(b0), "r"(b1));
}

// ldmatrix x4: lanes 0-7/8-15/16-23/24-31 give row addresses of 4 8x16B tiles
__device__ __forceinline__ void ldsm4(uint32_t a, uint32_t& r0, uint32_t& r1,
                                      uint32_t& r2, uint32_t& r3) {
    asm volatile("ldmatrix.sync.aligned.m8n8.x4.shared.b16 {%0,%1,%2,%3}, [%4];"
        : "=r"(r0), "=r"(r1), "=r"(r2), "=r"(r3) : "r"(a));
}

// ---------------- scratch ----------------
__device__ __nv_bfloat16 g_qt[CB * CH * CL * CC];  // [bh][l][c]
__device__ __nv_bfloat16 g_kt[CB * CH * CL * CC];  // [bh][l][c]
__device__ __nv_bfloat16 g_vv[CB * CH * CC * CL];  // [bh][d][l]
__device__ float g_att[CB * CO * CL];              // [(b*512 + h*64 + d)][l]

// ============================================================================
// QKV on HMMA. CTA = (64-seq tile, b, variant). 8 warps; warp w owns head w:
// out[m=o(64), n=l(64)] = W[o][c] x Y[l][c],  m16n8k16 bf16.
// smem: ysb bf16 [64 l][72 c] @0 (9216B); wsb bf16 [512 o][72 c] @9216 (73728B).
// Warp's wsb region (9216B) is reused to stage its output tile for 128B stores.
// ============================================================================
#define QKV_SMEM 82944

__global__ void __launch_bounds__(256) qkv_kernel(
    const float* __restrict__ x,
    const float* __restrict__ qdw, const float* __restrict__ qdb,
    const float* __restrict__ qpw, const float* __restrict__ qpb,
    const float* __restrict__ kdw, const float* __restrict__ kdb,
    const float* __restrict__ kpw, const float* __restrict__ kpb,
    const float* __restrict__ vdw, const float* __restrict__ vdb,
    const float* __restrict__ vpw, const float* __restrict__ vpb)
{
    extern __shared__ char qsm[];
    __nv_bfloat16* ysb = (__nv_bfloat16*)qsm;            // [64][72]
    __nv_bfloat16* wsb = (__nv_bfloat16*)(qsm + 9216);   // [512][72]

    int var = blockIdx.z;
    const float* dw = (var == 0) ? qdw : (var == 1) ? kdw : vdw;
    const float* db = (var == 0) ? qdb : (var == 1) ? kdb : vdb;
    const float* pw = (var == 0) ? qpw : (var == 1) ? kpw : vpw;
    const float* pb = (var == 0) ? qpb : (var == 1) ? kpb : vpb;
    float scale    = (var == 2) ? 1.0f : 0.35355339059327373f;

    int l0 = blockIdx.x * 64;
    int b  = blockIdx.y;
    int tid = threadIdx.x;
    int w = tid >> 5, ln = tid & 31, gp = ln >> 2, tg = ln & 3;

    // dwconv -> ysb[l][c] (bf16)
    for (int idx = tid; idx < 64 * 64; idx += 256) {
        int c = idx >> 6, li = idx & 63;
        int l = l0 + li;
        const float* xr = x + (size_t)(b * CC + c) * CL;
        float w0 = dw[c * 3 + 0], w1 = dw[c * 3 + 1], w2 = dw[c * 3 + 2];
        float xm = (l > 0)      ? xr[l - 1] : 0.f;
        float x0 = xr[l];
        float xp = (l < CL - 1) ? xr[l + 1] : 0.f;
        ysb[li * 72 + c] = __float2bfloat16(db[c] + w0 * xm + w1 * x0 + w2 * xp);
    }
    // weights fp32 -> bf16 wsb[o][c]
    for (int i = tid; i < 8192; i += 256) {
        int o = i >> 4, c4 = (i & 15) << 2;
        float4 wv = *(const float4*)&pw[(size_t)o * CC + c4];
        __nv_bfloat162 h0 = __floats2bfloat162_rn(wv.x, wv.y);
        __nv_bfloat162 h1 = __floats2bfloat162_rn(wv.z, wv.w);
        *(uint2*)&wsb[o * 72 + c4] = make_uint2(*(uint32_t*)&h0, *(uint32_t*)&h1);
    }
    __syncthreads();

    int obase = w * 64;
    float pbv[4][2];
    #pragma unroll
    for (int mt = 0; mt < 4; mt++) {
        pbv[mt][0] = pb[obase + mt * 16 + gp];
        pbv[mt][1] = pb[obase + mt * 16 + gp + 8];
    }

    float acc[4][8][4];
    #pragma unroll
    for (int mt = 0; mt < 4; mt++)
        #pragma unroll
        for (int n = 0; n < 8; n++)
            #pragma unroll
            for (int r = 0; r < 4; r++) acc[mt][n][r] = 0.f;

    #pragma unroll
    for (int ks = 0; ks < 4; ks++) {
        uint32_t af[4][4];
        #pragma unroll
        for (int mt = 0; mt < 4; mt++) {
            int row = obase + mt * 16 + gp;
            int col = ks * 16 + tg * 2;
            af[mt][0] = *(const uint32_t*)&wsb[(row)     * 72 + col];
            af[mt][1] = *(const uint32_t*)&wsb[(row + 8) * 72 + col];
            af[mt][2] = *(const uint32_t*)&wsb[(row)     * 72 + col + 8];
            af[mt][3] = *(const uint32_t*)&wsb[(row + 8) * 72 + col + 8];
        }
        #pragma unroll
        for (int n = 0; n < 8; n++) {
            int nrow = n * 8 + gp, ncol = ks * 16 + tg * 2;
            uint32_t b0 = *(const uint32_t*)&ysb[nrow * 72 + ncol];
            uint32_t b1 = *(const uint32_t*)&ysb[nrow * 72 + ncol + 8];
            #pragma unroll
            for (int mt = 0; mt < 4; mt++)
                hmma(acc[mt][n], af[mt][0], af[mt][1], af[mt][2], af[mt][3], b0, b1);
        }
    }

    // stage into this warp's (now dead) weight region
    __nv_bfloat16* stg = wsb + w * 4608;   // [64][72]
    if (var == 2) {
        // [d][l]: c0,c1 are adjacent l -> pack to one 32-bit store
        #pragma unroll
        for (int mt = 0; mt < 4; mt++)
            #pragma unroll
            for (int n = 0; n < 8; n++) {
                int d = mt * 16 + gp, lcol = n * 8 + tg * 2;
                __nv_bfloat162 h0 = __floats2bfloat162_rn(acc[mt][n][0] + pbv[mt][0],
                                                          acc[mt][n][1] + pbv[mt][0]);
                __nv_bfloat162 h1 = __floats2bfloat162_rn(acc[mt][n][2] + pbv[mt][1],
                                                          acc[mt][n][3] + pbv[mt][1]);
                *(uint32_t*)&stg[(d)     * 72 + lcol] = *(uint32_t*)&h0;
                *(uint32_t*)&stg[(d + 8) * 72 + lcol] = *(uint32_t*)&h1;
            }
    } else {
        // [l][d], scaled
        #pragma unroll
        for (int mt = 0; mt < 4; mt++)
            #pragma unroll
            for (int n = 0; n < 8; n++) {
                int d = mt * 16 + gp, lcol = n * 8 + tg * 2;
                stg[(lcol)     * 72 + d]     = __float2bfloat16((acc[mt][n][0] + pbv[mt][0]) * scale);
                stg[(lcol + 1) * 72 + d]     = __float2bfloat16((acc[mt][n][1] + pbv[mt][0]) * scale);
                stg[(lcol)     * 72 + d + 8] = __float2bfloat16((acc[mt][n][2] + pbv[mt][1]) * scale);
                stg[(lcol + 1) * 72 + d + 8] = __float2bfloat16((acc[mt][n][3] + pbv[mt][1]) * scale);
            }
    }
    __syncwarp();

    int bh = b * CH + w;
    if (var == 2) {
        for (int i = ln; i < 512; i += 32) {
            int r = i >> 3, j = i & 7;
            *(uint4*)&g_vv[((size_t)(bh * CC + r)) * CL + l0 + j * 8] =
                *(const uint4*)&stg[r * 72 + j * 8];
        }
    } else {
        __nv_bfloat16* outp = (var == 0) ? g_qt : g_kt;
        for (int i = ln; i < 512; i += 32) {
            int r = i >> 3, j = i & 7;
            *(uint4*)&outp[((size_t)bh * CL + l0 + r) * CC + j * 8] =
                *(const uint4*)&stg[r * 72 + j * 8];
        }
    }
}

// ============================================================================
// Flash attention on HMMA, ldmatrix fragment loads.
// ============================================================================
#define KT      64
#define NT      (CL / KT)
#define K_OFF0  33792
#define K_OFF1  43008
#define V_OFF0  52224
#define V_OFF1  61440
#define FL_SMEM 70656

__global__ void __launch_bounds__(128, 2) flash_kernel()
{
    extern __shared__ char sm[];
    uint32_t sb = smem_u32(sm);
    __nv_bfloat16* Qsm = (__nv_bfloat16*)sm;
    float* Osm = (float*)sm;

    int tid = threadIdx.x;
    int w   = tid >> 5;
    int ln  = tid & 31;
    int gp  = ln >> 2;
    int tg  = ln & 3;
    int l0  = blockIdx.x * 128;
    int bh  = blockIdx.z * CH + blockIdx.y;

    // ldmatrix per-lane row offset within a 2-n-group block (bytes)
    int t4 = ln >> 3;
    uint32_t lk = (((t4 >> 1) * 8 + (ln & 7)) * 144) + ((t4 & 1) * 16);

    const __nv_bfloat16* qg = g_qt + (size_t)bh * CL * CC;
    const __nv_bfloat16* kg = g_kt + (size_t)bh * CL * CC;
    const __nv_bfloat16* vg = g_vv + (size_t)bh * CC * CL;

    const uint32_t koff[2] = {K_OFF0, K_OFF1};
    const uint32_t voff[2] = {V_OFF0, V_OFF1};

    for (int c = tid; c < 1024; c += 128) {
        int r = c >> 3, j = c & 7;
        cpa16(sb + r * 144 + j * 16, qg + ((size_t)(l0 + r)) * CC + j * 8);
    }
    CP_COMMIT();
    for (int c = tid; c < 512; c += 128) {
        int r = c >> 3, j = c & 7;
        cpa16(sb + K_OFF0 + r * 144 + j * 16, kg + ((size_t)r) * CC + j * 8);
        cpa16(sb + V_OFF0 + r * 144 + j * 16, vg + (size_t)r * CL + j * 8);
    }
    CP_COMMIT();

    CP_WAIT(1);
    __syncthreads();
    uint32_t qa[2][4][4];
    #pragma unroll
    for (int mt = 0; mt < 2; mt++) {
        int row = w * 32 + mt * 16 + gp;
        #pragma unroll
        for (int ks = 0; ks < 4; ks++) {
            int col = ks * 16 + tg * 2;
            qa[mt][ks][0] = *(const uint32_t*)&Qsm[(row)     * 72 + col];
            qa[mt][ks][1] = *(const uint32_t*)&Qsm[(row + 8) * 72 + col];
            qa[mt][ks][2] = *(const uint32_t*)&Qsm[(row)     * 72 + col + 8];
            qa[mt][ks][3] = *(const uint32_t*)&Qsm[(row + 8) * 72 + col + 8];
        }
    }
    __syncthreads();

    float Oacc[2][8][4];
    #pragma unroll
    for (int mt = 0; mt < 2; mt++)
        #pragma unroll
        for (int n = 0; n < 8; n++)
            #pragma unroll
            for (int r = 0; r < 4; r++) Oacc[mt][n][r] = 0.f;
    float rs[2][2] = {{0.f, 0.f}, {0.f, 0.f}};

    for (int i = 0; i < NT; i++) {
        int buf = i & 1;
        if (i + 1 < NT) {
            int n0 = (i + 1) * KT;
            uint32_t kd = koff[buf ^ 1], vd = voff[buf ^ 1];
            for (int c = tid; c < 512; c += 128) {
                int r = c >> 3, j = c & 7;
                cpa16(sb + kd + r * 144 + j * 16, kg + ((size_t)(n0 + r)) * CC + j * 8);
                cpa16(sb + vd + r * 144 + j * 16, vg + (size_t)r * CL + n0 + j * 8);
            }
            CP_COMMIT();
            CP_WAIT(1);
        } else {
            CP_WAIT(0);
        }
        __syncthreads();

        uint32_t kbase = sb + koff[buf] + lk;
        uint32_t vbase = sb + voff[buf] + lk;

        // ---- MMA1: S = Q . K^T ----
        float Sacc[2][8][4];
        #pragma unroll
        for (int mt = 0; mt < 2; mt++)
            #pragma unroll
            for (int n = 0; n < 8; n++)
                #pragma unroll
                for (int r = 0; r < 4; r++) Sacc[mt][n][r] = 0.f;

        #pragma unroll
        for (int ks = 0; ks < 4; ks++) {
            uint32_t kb[8][2];
            #pragma unroll
            for (int ng2 = 0; ng2 < 4; ng2++)
                ldsm4(kbase + ng2 * 2304 + ks * 32,
                      kb[2 * ng2][0], kb[2 * ng2][1], kb[2 * ng2 + 1][0], kb[2 * ng2 + 1][1]);
            #pragma unroll
            for (int n = 0; n < 8; n++) {
                hmma(Sacc[0][n], qa[0][ks][0], qa[0][ks][1], qa[0][ks][2], qa[0][ks][3], kb[n][0], kb[n][1]);
                hmma(Sacc[1][n], qa[1][ks][0], qa[1][ks][1], qa[1][ks][2], qa[1][ks][3], kb[n][0], kb[n][1]);
            }
        }

        // ---- softmax (P = exp(S)) fused with MMA2: O += P . V ----
        #pragma unroll
        for (int ks = 0; ks < 4; ks++) {
            uint32_t vb[8][2];
            #pragma unroll
            for (int ng2 = 0; ng2 < 4; ng2++)
                ldsm4(vbase + ng2 * 2304 + ks * 32,
                      vb[2 * ng2][0], vb[2 * ng2][1], vb[2 * ng2 + 1][0], vb[2 * ng2 + 1][1]);
            #pragma unroll
            for (int mt = 0; mt < 2; mt++) {
                float e0 = __expf(Sacc[mt][2 * ks][0]);
                float e1 = __expf(Sacc[mt][2 * ks][1]);
                float e2 = __expf(Sacc[mt][2 * ks][2]);
                float e3 = __expf(Sacc[mt][2 * ks][3]);
                float f0 = __expf(Sacc[mt][2 * ks + 1][0]);
                float f1 = __expf(Sacc[mt][2 * ks + 1][1]);
                float f2 = __expf(Sacc[mt][2 * ks + 1][2]);
                float f3 = __expf(Sacc[mt][2 * ks + 1][3]);
                rs[mt][0] += (e0 + e1) + (f0 + f1);
                rs[mt][1] += (e2 + e3) + (f2 + f3);
                __nv_bfloat162 p0 = __floats2bfloat162_rn(e0, e1);
                __nv_bfloat162 p1 = __floats2bfloat162_rn(e2, e3);
                __nv_bfloat162 p2 = __floats2bfloat162_rn(f0, f1);
                __nv_bfloat162 p3 = __floats2bfloat162_rn(f2, f3);
                uint32_t pa0 = *(uint32_t*)&p0, pa1 = *(uint32_t*)&p1;
                uint32_t pa2 = *(uint32_t*)&p2, pa3 = *(uint32_t*)&p3;
                #pragma unroll
                for (int n = 0; n < 8; n++)
                    hmma(Oacc[mt][n], pa0, pa1, pa2, pa3, vb[n][0], vb[n][1]);
            }
        }
        __syncthreads();
    }

    #pragma unroll
    for (int mt = 0; mt < 2; mt++) {
        #pragma unroll
        for (int h = 0; h < 2; h++) {
            float v = rs[mt][h];
            v += __shfl_xor_sync(0xffffffffu, v, 1);
            v += __shfl_xor_sync(0xffffffffu, v, 2);
            rs[mt][h] = 1.0f / v;
        }
    }

    #pragma unroll
    for (int mt = 0; mt < 2; mt++) {
        int qb = w * 32 + mt * 16 + gp;
        #pragma unroll
        for (int n = 0; n < 8; n++) {
            int d = n * 8 + tg * 2;
            Osm[(d)     * 132 + qb]     = Oacc[mt][n][0] * rs[mt][0];
            Osm[(d + 1) * 132 + qb]     = Oacc[mt][n][1] * rs[mt][0];
            Osm[(d)     * 132 + qb + 8] = Oacc[mt][n][2] * rs[mt][1];
            Osm[(d + 1) * 132 + qb + 8] = Oacc[mt][n][3] * rs[mt][1];
        }
    }
    __syncthreads();

    float* ob = g_att + (size_t)bh * CC * CL + l0;
    for (int c = tid; c < 64 * 32; c += 128) {
        int d = c >> 5, q4 = (c & 31) << 2;
        *(float4*)&ob[(size_t)d * CL + q4] = *(const float4*)&Osm[d * 132 + q4];
    }
}

// ============================================================================
// Unify heads: CTA = (64-l tile, b), grid (32,4)=128 CTAs.
// per-thread 4c x 4l; smem as_[64 o][68 l], ws[64 o][68 c], reloaded per oc.
// ============================================================================
#define U_SMEM (2 * 64 * 68 * 4)

__global__ __launch_bounds__(256) void unify_kernel(
    const float* __restrict__ uw, const float* __restrict__ ub,
    float* __restrict__ y)
{
    extern __shared__ float usm[];
    float* as_ = usm;             // [64][68]
    float* ws  = usm + 64 * 68;   // [64][68]

    int tid = threadIdx.x;
    int tx = tid & 15, ty = tid >> 4;
    int l0 = blockIdx.x * 64, b = blockIdx.y;

    ull acc[4][2];
    #pragma unroll
    for (int i = 0; i < 4; i++) { acc[i][0] = 0ull; acc[i][1] = 0ull; }

    for (int oc = 0; oc < 8; oc++) {
        __syncthreads();
        for (int i = tid; i < 1024; i += 256) {
            int o = i >> 4, l4 = (i & 15) << 2;
            *(float4*)&as_[o * 68 + l4] =
                *(const float4*)&g_att[(size_t)(b * CO + oc * 64 + o) * CL + l0 + l4];
        }
        for (int i = tid; i < 1024; i += 256) {
            int c = i >> 4, o4 = (i & 15) << 2;
            float4 wv = *(const float4*)&uw[(size_t)c * CO + oc * 64 + o4];
            ws[(o4 + 0) * 68 + c] = wv.x;
            ws[(o4 + 1) * 68 + c] = wv.y;
            ws[(o4 + 2) * 68 + c] = wv.z;
            ws[(o4 + 3) * 68 + c] = wv.w;
        }
        __syncthreads();

        #pragma unroll 4
        for (int o = 0; o < 64; o++) {
            float4 av = *(const float4*)&as_[o * 68 + tx * 4];
            float4 wv = *(const float4*)&ws[o * 68 + ty * 4];
            ull a01 = f2pack(av.x, av.y), a23 = f2pack(av.z, av.w);
            float wf[4] = {wv.x, wv.y, wv.z, wv.w};
            #pragma unroll
            for (int cc = 0; cc < 4; cc++) {
                ull ww = f2pack(wf[cc], wf[cc]);
                acc[cc][0] = f2fma(ww, a01, acc[cc][0]);
                acc[cc][1] = f2fma(ww, a23, acc[cc][1]);
            }
        }
    }

    #pragma unroll
    for (int cc = 0; cc < 4; cc++) {
        int c = ty * 4 + cc;
        float bb = ub[c];
        float a0, a1, a2, a3;
        f2unpack(acc[cc][0], a0, a1);
        f2unpack(acc[cc][1], a2, a3);
        float4 r = make_float4(a0 + bb, a1 + bb, a2 + bb, a3 + bb);
        *(float4*)&y[(size_t)(b * CC + c) * CL + l0 + tx * 4] = r;
    }
}

// ============================================================================
extern "C" void kernel_launch(void* const* d_in, const int* in_sizes, int n_in,
                              void* d_out, int out_size)
{
    (void)in_sizes; (void)n_in; (void)out_size;
    const float* x    = (const float*)d_in[0];
    const float* q_dw = (const float*)d_in[1];
    const float* q_db = (const float*)d_in[2];
    const float* q_pw = (const float*)d_in[3];
    const float* q_pb = (const float*)d_in[4];
    const float* k_dw = (const float*)d_in[5];
    const float* k_db = (const float*)d_in[6];
    const float* k_pw = (const float*)d_in[7];
    const float* k_pb = (const float*)d_in[8];
    const float* v_dw = (const float*)d_in[9];
    const float* v_db = (const float*)d_in[10];
    const float* v_pw = (const float*)d_in[11];
    const float* v_pb = (const float*)d_in[12];
    const float* u_w  = (const float*)d_in[13];
    const float* u_b  = (const float*)d_in[14];

    cudaFuncSetAttribute(qkv_kernel,
                         cudaFuncAttributeMaxDynamicSharedMemorySize, QKV_SMEM);
    cudaFuncSetAttribute(flash_kernel,
                         cudaFuncAttributeMaxDynamicSharedMemorySize, FL_SMEM);

    qkv_kernel<<<dim3(CL / 64, CB, 3), 256, QKV_SMEM>>>(
        x, q_dw, q_db, q_pw, q_pb, k_dw, k_db, k_pw, k_pb, v_dw, v_db, v_pw, v_pb);

    flash_kernel<<<dim3(CL / 128, CH, CB), 128, FL_SMEM>>>();

    unify_kernel<<<dim3(CL / 64, CB), 256, U_SMEM>>>(u_w, u_b, (float*)d_out);
}

// round 5
// speedup vs baseline: 6.1328x; 1.0395x over previous
#include <cuda_runtime.h>
#include <cuda_bf16.h>
#include <cstdint>

#define CB 4
#define CC 64
#define CH 8
#define CL 2048
#define CO 512

typedef unsigned long long ull;

// ---------------- packed f32x2 helpers ----------------
__device__ __forceinline__ ull f2pack(float lo, float hi) {
    ull d; asm("mov.b64 %0, {%1, %2};" : "=l"(d) : "f"(lo), "f"(hi)); return d;
}
__device__ __forceinline__ void f2unpack(ull v, float& lo, float& hi) {
    asm("mov.b64 {%0, %1}, %2;" : "=f"(lo), "=f"(hi) : "l"(v));
}
__device__ __forceinline__ ull f2fma(ull a, ull b, ull c) {
    ull d; asm("fma.rn.f32x2 %0, %1, %2, %3;" : "=l"(d) : "l"(a), "l"(b), "l"(c)); return d;
}

// ---------------- cp.async ----------------
__device__ __forceinline__ void cpa16(uint32_t s, const void* g) {
    asm volatile("cp.async.cg.shared.global [%0], [%1], 16;" :: "r"(s), "l"(g));
}
#define CP_COMMIT() asm volatile("cp.async.commit_group;" ::: "memory")
#define CP_WAIT(n)  asm volatile("cp.async.wait_group %0;" :: "n"(n) : "memory")

__device__ __forceinline__ uint32_t smem_u32(const void* p) {
    uint32_t a;
    asm("{ .reg .u64 t; cvta.to.shared.u64 t, %1; cvt.u32.u64 %0, t; }" : "=r"(a) : "l"(p));
    return a;
}

// ---------------- HMMA m16n8k16 bf16 ----------------
__device__ __forceinline__ void hmma(float* c,
                                     uint32_t a0, uint32_t a1, uint32_t a2, uint32_t a3,
                                     uint32_t b0, uint32_t b1) {
    asm volatile(
        "mma.sync.aligned.m16n8k16.row.col.f32.bf16.bf16.f32 "
        "{%0,%1,%2,%3},{%4,%5,%6,%7},{%8,%9},{%0,%1,%2,%3};"
        : "+f"(c[0]), "+f"(c[1]), "+f"(c[2]), "+f"(c[3])
        : "r"(a0), "r"(a1), "r"(a2), "r"(a3), "r"(b0), "r"(b1));
}

__device__ __forceinline__ void ldsm4(uint32_t a, uint32_t& r0, uint32_t& r1,
                                      uint32_t& r2, uint32_t& r3) {
    asm volatile("ldmatrix.sync.aligned.m8n8.x4.shared.b16 {%0,%1,%2,%3}, [%4];"
        : "=r"(r0), "=r"(r1), "=r"(r2), "=r"(r3) : "r"(a));
}

// ---------------- scratch ----------------
__device__ __nv_bfloat16 g_qt[CB * CH * CL * CC];   // [bh][l][c]
__device__ __nv_bfloat16 g_kt[CB * CH * CL * CC];   // [bh][l][c]
__device__ __nv_bfloat16 g_vv[CB * CH * CC * CL];   // [bh][d][l]
__device__ float g_att[CB * CO * CL];               // [(b*512 + h*64 + d)][l]
__device__ __nv_bfloat16 g_w[3 * CO * CC];          // preconverted pw (q,k prescaled)

// ============================================================================
// Prep: convert pointwise weights fp32 -> bf16, fold C^-0.25 into q/k weights.
// ============================================================================
__global__ __launch_bounds__(256) void prep_kernel(
    const float* __restrict__ qpw, const float* __restrict__ kpw,
    const float* __restrict__ vpw)
{
    int i = blockIdx.x * 256 + threadIdx.x;   // one float4 per thread, 24576 total
    int var = i / 8192;
    int off = (i - var * 8192) * 4;
    const float* src = (var == 0) ? qpw : (var == 1) ? kpw : vpw;
    float s = (var == 2) ? 1.0f : 0.35355339059327373f;
    float4 wv = *(const float4*)&src[off];
    __nv_bfloat162 h0 = __floats2bfloat162_rn(wv.x * s, wv.y * s);
    __nv_bfloat162 h1 = __floats2bfloat162_rn(wv.z * s, wv.w * s);
    *(uint2*)&g_w[var * (CO * CC) + off] = make_uint2(*(uint32_t*)&h0, *(uint32_t*)&h1);
}

// ============================================================================
// QKV on HMMA. CTA = (64-seq tile, b, variant). 8 warps; warp w owns head w.
// Weights arrive via cp.async from preconverted g_w (overlaps dwconv).
// ============================================================================
#define QKV_SMEM 82944

__global__ void __launch_bounds__(256) qkv_kernel(
    const float* __restrict__ x,
    const float* __restrict__ qdw, const float* __restrict__ qdb,
    const float* __restrict__ qpb,
    const float* __restrict__ kdw, const float* __restrict__ kdb,
    const float* __restrict__ kpb,
    const float* __restrict__ vdw, const float* __restrict__ vdb,
    const float* __restrict__ vpb)
{
    extern __shared__ char qsm[];
    __nv_bfloat16* ysb = (__nv_bfloat16*)qsm;            // [64 l][72 c]
    __nv_bfloat16* wsb = (__nv_bfloat16*)(qsm + 9216);   // [512 o][72 c]
    uint32_t sb = smem_u32(qsm);

    int var = blockIdx.z;
    const float* dw = (var == 0) ? qdw : (var == 1) ? kdw : vdw;
    const float* db = (var == 0) ? qdb : (var == 1) ? kdb : vdb;
    const float* pb = (var == 0) ? qpb : (var == 1) ? kpb : vpb;
    float bscale   = (var == 2) ? 1.0f : 0.35355339059327373f;

    int l0 = blockIdx.x * 64;
    int b  = blockIdx.y;
    int tid = threadIdx.x;
    int w = tid >> 5, ln = tid & 31, gp = ln >> 2, tg = ln & 3;

    // kick off weight cp.async first (overlaps the dwconv global loads)
    const __nv_bfloat16* wg = g_w + (size_t)var * (CO * CC);
    for (int i = tid; i < 4096; i += 256) {
        int r = i >> 3, j = i & 7;
        cpa16(sb + 9216 + r * 144 + j * 16, wg + (size_t)r * CC + j * 8);
    }
    CP_COMMIT();

    // dwconv -> ysb[l][c] (bf16)
    for (int idx = tid; idx < 64 * 64; idx += 256) {
        int c = idx >> 6, li = idx & 63;
        int l = l0 + li;
        const float* xr = x + (size_t)(b * CC + c) * CL;
        float w0 = dw[c * 3 + 0], w1 = dw[c * 3 + 1], w2 = dw[c * 3 + 2];
        float xm = (l > 0)      ? xr[l - 1] : 0.f;
        float x0 = xr[l];
        float xp = (l < CL - 1) ? xr[l + 1] : 0.f;
        ysb[li * 72 + c] = __float2bfloat16(db[c] + w0 * xm + w1 * x0 + w2 * xp);
    }
    CP_WAIT(0);
    __syncthreads();

    int obase = w * 64;
    float pbv[4][2];
    #pragma unroll
    for (int mt = 0; mt < 4; mt++) {
        pbv[mt][0] = pb[obase + mt * 16 + gp] * bscale;
        pbv[mt][1] = pb[obase + mt * 16 + gp + 8] * bscale;
    }

    float acc[4][8][4];
    #pragma unroll
    for (int mt = 0; mt < 4; mt++)
        #pragma unroll
        for (int n = 0; n < 8; n++)
            #pragma unroll
            for (int r = 0; r < 4; r++) acc[mt][n][r] = 0.f;

    #pragma unroll
    for (int ks = 0; ks < 4; ks++) {
        uint32_t af[4][4];
        #pragma unroll
        for (int mt = 0; mt < 4; mt++) {
            int row = obase + mt * 16 + gp;
            int col = ks * 16 + tg * 2;
            af[mt][0] = *(const uint32_t*)&wsb[(row)     * 72 + col];
            af[mt][1] = *(const uint32_t*)&wsb[(row + 8) * 72 + col];
            af[mt][2] = *(const uint32_t*)&wsb[(row)     * 72 + col + 8];
            af[mt][3] = *(const uint32_t*)&wsb[(row + 8) * 72 + col + 8];
        }
        #pragma unroll
        for (int n = 0; n < 8; n++) {
            int nrow = n * 8 + gp, ncol = ks * 16 + tg * 2;
            uint32_t b0 = *(const uint32_t*)&ysb[nrow * 72 + ncol];
            uint32_t b1 = *(const uint32_t*)&ysb[nrow * 72 + ncol + 8];
            #pragma unroll
            for (int mt = 0; mt < 4; mt++)
                hmma(acc[mt][n], af[mt][0], af[mt][1], af[mt][2], af[mt][3], b0, b1);
        }
    }

    // stage into this warp's (now dead) weight region
    __nv_bfloat16* stg = wsb + w * 4608;   // [64][72]
    if (var == 2) {
        #pragma unroll
        for (int mt = 0; mt < 4; mt++)
            #pragma unroll
            for (int n = 0; n < 8; n++) {
                int d = mt * 16 + gp, lcol = n * 8 + tg * 2;
                __nv_bfloat162 h0 = __floats2bfloat162_rn(acc[mt][n][0] + pbv[mt][0],
                                                          acc[mt][n][1] + pbv[mt][0]);
                __nv_bfloat162 h1 = __floats2bfloat162_rn(acc[mt][n][2] + pbv[mt][1],
                                                          acc[mt][n][3] + pbv[mt][1]);
                *(uint32_t*)&stg[(d)     * 72 + lcol] = *(uint32_t*)&h0;
                *(uint32_t*)&stg[(d + 8) * 72 + lcol] = *(uint32_t*)&h1;
            }
    } else {
        #pragma unroll
        for (int mt = 0; mt < 4; mt++)
            #pragma unroll
            for (int n = 0; n < 8; n++) {
                int d = mt * 16 + gp, lcol = n * 8 + tg * 2;
                stg[(lcol)     * 72 + d]     = __float2bfloat16(acc[mt][n][0] + pbv[mt][0]);
                stg[(lcol + 1) * 72 + d]     = __float2bfloat16(acc[mt][n][1] + pbv[mt][0]);
                stg[(lcol)     * 72 + d + 8] = __float2bfloat16(acc[mt][n][2] + pbv[mt][1]);
                stg[(lcol + 1) * 72 + d + 8] = __float2bfloat16(acc[mt][n][3] + pbv[mt][1]);
            }
    }
    __syncwarp();

    int bh = b * CH + w;
    if (var == 2) {
        for (int i = ln; i < 512; i += 32) {
            int r = i >> 3, j = i & 7;
            *(uint4*)&g_vv[((size_t)(bh * CC + r)) * CL + l0 + j * 8] =
                *(const uint4*)&stg[r * 72 + j * 8];
        }
    } else {
        __nv_bfloat16* outp = (var == 0) ? g_qt : g_kt;
        for (int i = ln; i < 512; i += 32) {
            int r = i >> 3, j = i & 7;
            *(uint4*)&outp[((size_t)bh * CL + l0 + r) * CC + j * 8] =
                *(const uint4*)&stg[r * 72 + j * 8];
        }
    }
}

// ============================================================================
// Flash attention on HMMA. 3-buffer cp.async pipeline, ONE barrier per tile:
// the top-of-iteration barrier proves all warps finished tile i-1, so tile i+2
// may overwrite buf (i+2)%3 == (i-1)%3. Warps drift within the iteration, so
// one warp's exp overlaps another's HMMA.
// SMEM: Q [0,18432) (reused as Osm at end); buf j at 18432 + j*18432 (K, then V).
// ============================================================================
#define KT      64
#define NT      (CL / KT)
#define KV_OFF  18432
#define KV_STR  18432
#define FL_SMEM 73728

__global__ void __launch_bounds__(128, 2) flash_kernel()
{
    extern __shared__ char sm[];
    uint32_t sb = smem_u32(sm);
    __nv_bfloat16* Qsm = (__nv_bfloat16*)sm;
    float* Osm = (float*)sm;

    int tid = threadIdx.x;
    int w   = tid >> 5;
    int ln  = tid & 31;
    int gp  = ln >> 2;
    int tg  = ln & 3;
    int l0  = blockIdx.x * 128;
    int bh  = blockIdx.z * CH + blockIdx.y;

    int t4 = ln >> 3;
    uint32_t lk = (((t4 >> 1) * 8 + (ln & 7)) * 144) + ((t4 & 1) * 16);

    const __nv_bfloat16* qg = g_qt + (size_t)bh * CL * CC;
    const __nv_bfloat16* kg = g_kt + (size_t)bh * CL * CC;
    const __nv_bfloat16* vg = g_vv + (size_t)bh * CC * CL;

    // Q (group 1)
    for (int c = tid; c < 1024; c += 128) {
        int r = c >> 3, j = c & 7;
        cpa16(sb + r * 144 + j * 16, qg + ((size_t)(l0 + r)) * CC + j * 8);
    }
    CP_COMMIT();
    // tile 0 -> buf 0 (group 2), tile 1 -> buf 1 (group 3)
    #pragma unroll
    for (int t = 0; t < 2; t++) {
        uint32_t base = sb + KV_OFF + t * KV_STR;
        int n0 = t * KT;
        for (int c = tid; c < 512; c += 128) {
            int r = c >> 3, j = c & 7;
            cpa16(base + r * 144 + j * 16, kg + ((size_t)(n0 + r)) * CC + j * 8);
            cpa16(base + 9216 + r * 144 + j * 16, vg + (size_t)r * CL + n0 + j * 8);
        }
        CP_COMMIT();
    }

    // Q fragments
    CP_WAIT(2);
    __syncthreads();
    uint32_t qa[2][4][4];
    #pragma unroll
    for (int mt = 0; mt < 2; mt++) {
        int row = w * 32 + mt * 16 + gp;
        #pragma unroll
        for (int ks = 0; ks < 4; ks++) {
            int col = ks * 16 + tg * 2;
            qa[mt][ks][0] = *(const uint32_t*)&Qsm[(row)     * 72 + col];
            qa[mt][ks][1] = *(const uint32_t*)&Qsm[(row + 8) * 72 + col];
            qa[mt][ks][2] = *(const uint32_t*)&Qsm[(row)     * 72 + col + 8];
            qa[mt][ks][3] = *(const uint32_t*)&Qsm[(row + 8) * 72 + col + 8];
        }
    }

    float Oacc[2][8][4];
    #pragma unroll
    for (int mt = 0; mt < 2; mt++)
        #pragma unroll
        for (int n = 0; n < 8; n++)
            #pragma unroll
            for (int r = 0; r < 4; r++) Oacc[mt][n][r] = 0.f;
    float rs[2][2] = {{0.f, 0.f}, {0.f, 0.f}};

    int cur = 0, pf = 2;
    for (int i = 0; i < NT; i++) {
        if (i + 1 < NT) { CP_WAIT(1); } else { CP_WAIT(0); }
        __syncthreads();   // tile i visible; all warps done with tile i-1

        if (i + 2 < NT) {
            int n0 = (i + 2) * KT;
            uint32_t base = sb + KV_OFF + pf * KV_STR;
            for (int c = tid; c < 512; c += 128) {
                int r = c >> 3, j = c & 7;
                cpa16(base + r * 144 + j * 16, kg + ((size_t)(n0 + r)) * CC + j * 8);
                cpa16(base + 9216 + r * 144 + j * 16, vg + (size_t)r * CL + n0 + j * 8);
            }
            CP_COMMIT();
        }

        uint32_t kbase = sb + KV_OFF + cur * KV_STR + lk;
        uint32_t vbase = kbase + 9216;

        // ---- MMA1: S = Q . K^T ----
        float Sacc[2][8][4];
        #pragma unroll
        for (int mt = 0; mt < 2; mt++)
            #pragma unroll
            for (int n = 0; n < 8; n++)
                #pragma unroll
                for (int r = 0; r < 4; r++) Sacc[mt][n][r] = 0.f;

        #pragma unroll
        for (int ks = 0; ks < 4; ks++) {
            uint32_t kb[8][2];
            #pragma unroll
            for (int ng2 = 0; ng2 < 4; ng2++)
                ldsm4(kbase + ng2 * 2304 + ks * 32,
                      kb[2 * ng2][0], kb[2 * ng2][1], kb[2 * ng2 + 1][0], kb[2 * ng2 + 1][1]);
            #pragma unroll
            for (int n = 0; n < 8; n++) {
                hmma(Sacc[0][n], qa[0][ks][0], qa[0][ks][1], qa[0][ks][2], qa[0][ks][3], kb[n][0], kb[n][1]);
                hmma(Sacc[1][n], qa[1][ks][0], qa[1][ks][1], qa[1][ks][2], qa[1][ks][3], kb[n][0], kb[n][1]);
            }
        }

        // ---- softmax (P = exp(S)) fused with MMA2: O += P . V ----
        #pragma unroll
        for (int ks = 0; ks < 4; ks++) {
            uint32_t vb[8][2];
            #pragma unroll
            for (int ng2 = 0; ng2 < 4; ng2++)
                ldsm4(vbase + ng2 * 2304 + ks * 32,
                      vb[2 * ng2][0], vb[2 * ng2][1], vb[2 * ng2 + 1][0], vb[2 * ng2 + 1][1]);
            #pragma unroll
            for (int mt = 0; mt < 2; mt++) {
                float e0 = __expf(Sacc[mt][2 * ks][0]);
                float e1 = __expf(Sacc[mt][2 * ks][1]);
                float e2 = __expf(Sacc[mt][2 * ks][2]);
                float e3 = __expf(Sacc[mt][2 * ks][3]);
                float f0 = __expf(Sacc[mt][2 * ks + 1][0]);
                float f1 = __expf(Sacc[mt][2 * ks + 1][1]);
                float f2 = __expf(Sacc[mt][2 * ks + 1][2]);
                float f3 = __expf(Sacc[mt][2 * ks + 1][3]);
                rs[mt][0] += (e0 + e1) + (f0 + f1);
                rs[mt][1] += (e2 + e3) + (f2 + f3);
                __nv_bfloat162 p0 = __floats2bfloat162_rn(e0, e1);
                __nv_bfloat162 p1 = __floats2bfloat162_rn(e2, e3);
                __nv_bfloat162 p2 = __floats2bfloat162_rn(f0, f1);
                __nv_bfloat162 p3 = __floats2bfloat162_rn(f2, f3);
                uint32_t pa0 = *(uint32_t*)&p0, pa1 = *(uint32_t*)&p1;
                uint32_t pa2 = *(uint32_t*)&p2, pa3 = *(uint32_t*)&p3;
                #pragma unroll
                for (int n = 0; n < 8; n++)
                    hmma(Oacc[mt][n], pa0, pa1, pa2, pa3, vb[n][0], vb[n][1]);
            }
        }

        cur = (cur == 2) ? 0 : cur + 1;
        pf  = (pf  == 2) ? 0 : pf  + 1;
    }

    #pragma unroll
    for (int mt = 0; mt < 2; mt++) {
        #pragma unroll
        for (int h = 0; h < 2; h++) {
            float v = rs[mt][h];
            v += __shfl_xor_sync(0xffffffffu, v, 1);
            v += __shfl_xor_sync(0xffffffffu, v, 2);
            rs[mt][h] = 1.0f / v;
        }
    }

    __syncthreads();   // everyone past Qsm use (frags long extracted); reuse as Osm
    #pragma unroll
    for (int mt = 0; mt < 2; mt++) {
        int qb = w * 32 + mt * 16 + gp;
        #pragma unroll
        for (int n = 0; n < 8; n++) {
            int d = n * 8 + tg * 2;
            Osm[(d)     * 132 + qb]     = Oacc[mt][n][0] * rs[mt][0];
            Osm[(d + 1) * 132 + qb]     = Oacc[mt][n][1] * rs[mt][0];
            Osm[(d)     * 132 + qb + 8] = Oacc[mt][n][2] * rs[mt][1];
            Osm[(d + 1) * 132 + qb + 8] = Oacc[mt][n][3] * rs[mt][1];
        }
    }
    __syncthreads();

    float* ob = g_att + (size_t)bh * CC * CL + l0;
    for (int c = tid; c < 64 * 32; c += 128) {
        int d = c >> 5, q4 = (c & 31) << 2;
        *(float4*)&ob[(size_t)d * CL + q4] = *(const float4*)&Osm[d * 132 + q4];
    }
}

// ============================================================================
// Unify heads: CTA = (64-l tile, b), grid (32,4)=128 CTAs.
// ============================================================================
#define U_SMEM (2 * 64 * 68 * 4)

__global__ __launch_bounds__(256) void unify_kernel(
    const float* __restrict__ uw, const float* __restrict__ ub,
    float* __restrict__ y)
{
    extern __shared__ float usm[];
    float* as_ = usm;             // [64][68]
    float* ws  = usm + 64 * 68;   // [64][68]

    int tid = threadIdx.x;
    int tx = tid & 15, ty = tid >> 4;
    int l0 = blockIdx.x * 64, b = blockIdx.y;

    ull acc[4][2];
    #pragma unroll
    for (int i = 0; i < 4; i++) { acc[i][0] = 0ull; acc[i][1] = 0ull; }

    for (int oc = 0; oc < 8; oc++) {
        __syncthreads();
        for (int i = tid; i < 1024; i += 256) {
            int o = i >> 4, l4 = (i & 15) << 2;
            *(float4*)&as_[o * 68 + l4] =
                *(const float4*)&g_att[(size_t)(b * CO + oc * 64 + o) * CL + l0 + l4];
        }
        for (int i = tid; i < 1024; i += 256) {
            int c = i >> 4, o4 = (i & 15) << 2;
            float4 wv = *(const float4*)&uw[(size_t)c * CO + oc * 64 + o4];
            ws[(o4 + 0) * 68 + c] = wv.x;
            ws[(o4 + 1) * 68 + c] = wv.y;
            ws[(o4 + 2) * 68 + c] = wv.z;
            ws[(o4 + 3) * 68 + c] = wv.w;
        }
        __syncthreads();

        #pragma unroll 4
        for (int o = 0; o < 64; o++) {
            float4 av = *(const float4*)&as_[o * 68 + tx * 4];
            float4 wv = *(const float4*)&ws[o * 68 + ty * 4];
            ull a01 = f2pack(av.x, av.y), a23 = f2pack(av.z, av.w);
            float wf[4] = {wv.x, wv.y, wv.z, wv.w};
            #pragma unroll
            for (int cc = 0; cc < 4; cc++) {
                ull ww = f2pack(wf[cc], wf[cc]);
                acc[cc][0] = f2fma(ww, a01, acc[cc][0]);
                acc[cc][1] = f2fma(ww, a23, acc[cc][1]);
            }
        }
    }

    #pragma unroll
    for (int cc = 0; cc < 4; cc++) {
        int c = ty * 4 + cc;
        float bb = ub[c];
        float a0, a1, a2, a3;
        f2unpack(acc[cc][0], a0, a1);
        f2unpack(acc[cc][1], a2, a3);
        float4 r = make_float4(a0 + bb, a1 + bb, a2 + bb, a3 + bb);
        *(float4*)&y[(size_t)(b * CC + c) * CL + l0 + tx * 4] = r;
    }
}

// ============================================================================
extern "C" void kernel_launch(void* const* d_in, const int* in_sizes, int n_in,
                              void* d_out, int out_size)
{
    (void)in_sizes; (void)n_in; (void)out_size;
    const float* x    = (const float*)d_in[0];
    const float* q_dw = (const float*)d_in[1];
    const float* q_db = (const float*)d_in[2];
    const float* q_pw = (const float*)d_in[3];
    const float* q_pb = (const float*)d_in[4];
    const float* k_dw = (const float*)d_in[5];
    const float* k_db = (const float*)d_in[6];
    const float* k_pw = (const float*)d_in[7];
    const float* k_pb = (const float*)d_in[8];
    const float* v_dw = (const float*)d_in[9];
    const float* v_db = (const float*)d_in[10];
    const float* v_pw = (const float*)d_in[11];
    const float* v_pb = (const float*)d_in[12];
    const float* u_w  = (const float*)d_in[13];
    const float* u_b  = (const float*)d_in[14];

    cudaFuncSetAttribute(qkv_kernel,
                         cudaFuncAttributeMaxDynamicSharedMemorySize, QKV_SMEM);
    cudaFuncSetAttribute(flash_kernel,
                         cudaFuncAttributeMaxDynamicSharedMemorySize, FL_SMEM);

    prep_kernel<<<96, 256>>>(q_pw, k_pw, v_pw);

    qkv_kernel<<<dim3(CL / 64, CB, 3), 256, QKV_SMEM>>>(
        x, q_dw, q_db, q_pb, k_dw, k_db, k_pb, v_dw, v_db, v_pb);

    flash_kernel<<<dim3(CL / 128, CH, CB), 128, FL_SMEM>>>();

    unify_kernel<<<dim3(CL / 64, CB), 256, U_SMEM>>>(u_w, u_b, (float*)d_out);
}

// round 6
// speedup vs baseline: 7.1359x; 1.1636x over previous
#include <cuda_runtime.h>
#include <cuda_bf16.h>
#include <cstdint>

#define CB 4
#define CC 64
#define CH 8
#define CL 2048
#define CO 512

#define QK_SCALE 0.35355339059327373f
#define LOG2E    1.4426950408889634f

typedef unsigned long long ull;

// ---------------- packed f32x2 helpers ----------------
__device__ __forceinline__ ull f2pack(float lo, float hi) {
    ull d; asm("mov.b64 %0, {%1, %2};" : "=l"(d) : "f"(lo), "f"(hi)); return d;
}
__device__ __forceinline__ void f2unpack(ull v, float& lo, float& hi) {
    asm("mov.b64 {%0, %1}, %2;" : "=f"(lo), "=f"(hi) : "l"(v));
}
__device__ __forceinline__ ull f2fma(ull a, ull b, ull c) {
    ull d; asm("fma.rn.f32x2 %0, %1, %2, %3;" : "=l"(d) : "l"(a), "l"(b), "l"(c)); return d;
}

// ---------------- bf16x2 exp2 path ----------------
__device__ __forceinline__ uint32_t cvt2bf(float hi, float lo) {
    uint32_t d; asm("cvt.rn.bf16x2.f32 %0, %1, %2;" : "=r"(d) : "f"(hi), "f"(lo)); return d;
}
__device__ __forceinline__ uint32_t ex2bf2(uint32_t x) {
    uint32_t d; asm("ex2.approx.ftz.bf16x2 %0, %1;" : "=r"(d) : "r"(x)); return d;
}
#define ONESBF 0x3F803F80u

// ---------------- cp.async ----------------
__device__ __forceinline__ void cpa16(uint32_t s, const void* g) {
    asm volatile("cp.async.cg.shared.global [%0], [%1], 16;" :: "r"(s), "l"(g));
}
#define CP_COMMIT() asm volatile("cp.async.commit_group;" ::: "memory")
#define CP_WAIT(n)  asm volatile("cp.async.wait_group %0;" :: "n"(n) : "memory")

__device__ __forceinline__ uint32_t smem_u32(const void* p) {
    uint32_t a;
    asm("{ .reg .u64 t; cvta.to.shared.u64 t, %1; cvt.u32.u64 %0, t; }" : "=r"(a) : "l"(p));
    return a;
}

// ---------------- HMMA m16n8k16 bf16 ----------------
__device__ __forceinline__ void hmma(float* c,
                                     uint32_t a0, uint32_t a1, uint32_t a2, uint32_t a3,
                                     uint32_t b0, uint32_t b1) {
    asm volatile(
        "mma.sync.aligned.m16n8k16.row.col.f32.bf16.bf16.f32 "
        "{%0,%1,%2,%3},{%4,%5,%6,%7},{%8,%9},{%0,%1,%2,%3};"
        : "+f"(c[0]), "+f"(c[1]), "+f"(c[2]), "+f"(c[3])
        : "r"(a0), "r"(a1), "r"(a2), "r"(a3), "r"(b0), "r"(b1));
}

__device__ __forceinline__ void ldsm4(uint32_t a, uint32_t& r0, uint32_t& r1,
                                      uint32_t& r2, uint32_t& r3) {
    asm volatile("ldmatrix.sync.aligned.m8n8.x4.shared.b16 {%0,%1,%2,%3}, [%4];"
        : "=r"(r0), "=r"(r1), "=r"(r2), "=r"(r3) : "r"(a));
}

// ---------------- scratch ----------------
__device__ __nv_bfloat16 g_qt[CB * CH * CL * CC];   // [bh][l][c]  (q prescaled by QK_SCALE*LOG2E)
__device__ __nv_bfloat16 g_kt[CB * CH * CL * CC];   // [bh][l][c]
__device__ __nv_bfloat16 g_vv[CB * CH * CC * CL];   // [bh][d][l]
__device__ float g_att[CB * CO * CL];               // [(b*512 + h*64 + d)][l]
__device__ __nv_bfloat16 g_w[3 * CO * CC];          // preconverted pw (scales folded)

// ============================================================================
// Prep: convert pointwise weights fp32 -> bf16; fold C^-0.25 (and log2e for q).
// ============================================================================
__global__ __launch_bounds__(256) void prep_kernel(
    const float* __restrict__ qpw, const float* __restrict__ kpw,
    const float* __restrict__ vpw)
{
    int i = blockIdx.x * 256 + threadIdx.x;
    int var = i / 8192;
    int off = (i - var * 8192) * 4;
    const float* src = (var == 0) ? qpw : (var == 1) ? kpw : vpw;
    float s = (var == 0) ? QK_SCALE * LOG2E : (var == 1) ? QK_SCALE : 1.0f;
    float4 wv = *(const float4*)&src[off];
    __nv_bfloat162 h0 = __floats2bfloat162_rn(wv.x * s, wv.y * s);
    __nv_bfloat162 h1 = __floats2bfloat162_rn(wv.z * s, wv.w * s);
    *(uint2*)&g_w[var * (CO * CC) + off] = make_uint2(*(uint32_t*)&h0, *(uint32_t*)&h1);
}

// ============================================================================
// QKV on HMMA. CTA = (64-seq tile, b, variant). 8 warps; warp w owns head w.
// ============================================================================
#define QKV_SMEM 82944

__global__ void __launch_bounds__(256) qkv_kernel(
    const float* __restrict__ x,
    const float* __restrict__ qdw, const float* __restrict__ qdb,
    const float* __restrict__ qpb,
    const float* __restrict__ kdw, const float* __restrict__ kdb,
    const float* __restrict__ kpb,
    const float* __restrict__ vdw, const float* __restrict__ vdb,
    const float* __restrict__ vpb)
{
    extern __shared__ char qsm[];
    __nv_bfloat16* ysb = (__nv_bfloat16*)qsm;            // [64 l][72 c]
    __nv_bfloat16* wsb = (__nv_bfloat16*)(qsm + 9216);   // [512 o][72 c]
    uint32_t sb = smem_u32(qsm);

    int var = blockIdx.z;
    const float* dw = (var == 0) ? qdw : (var == 1) ? kdw : vdw;
    const float* db = (var == 0) ? qdb : (var == 1) ? kdb : vdb;
    const float* pb = (var == 0) ? qpb : (var == 1) ? kpb : vpb;
    float bscale   = (var == 0) ? QK_SCALE * LOG2E : (var == 1) ? QK_SCALE : 1.0f;

    int l0 = blockIdx.x * 64;
    int b  = blockIdx.y;
    int tid = threadIdx.x;
    int w = tid >> 5, ln = tid & 31, gp = ln >> 2, tg = ln & 3;

    const __nv_bfloat16* wg = g_w + (size_t)var * (CO * CC);
    for (int i = tid; i < 4096; i += 256) {
        int r = i >> 3, j = i & 7;
        cpa16(sb + 9216 + r * 144 + j * 16, wg + (size_t)r * CC + j * 8);
    }
    CP_COMMIT();

    for (int idx = tid; idx < 64 * 64; idx += 256) {
        int c = idx >> 6, li = idx & 63;
        int l = l0 + li;
        const float* xr = x + (size_t)(b * CC + c) * CL;
        float w0 = dw[c * 3 + 0], w1 = dw[c * 3 + 1], w2 = dw[c * 3 + 2];
        float xm = (l > 0)      ? xr[l - 1] : 0.f;
        float x0 = xr[l];
        float xp = (l < CL - 1) ? xr[l + 1] : 0.f;
        ysb[li * 72 + c] = __float2bfloat16(db[c] + w0 * xm + w1 * x0 + w2 * xp);
    }
    CP_WAIT(0);
    __syncthreads();

    int obase = w * 64;
    float pbv[4][2];
    #pragma unroll
    for (int mt = 0; mt < 4; mt++) {
        pbv[mt][0] = pb[obase + mt * 16 + gp] * bscale;
        pbv[mt][1] = pb[obase + mt * 16 + gp + 8] * bscale;
    }

    float acc[4][8][4];
    #pragma unroll
    for (int mt = 0; mt < 4; mt++)
        #pragma unroll
        for (int n = 0; n < 8; n++)
            #pragma unroll
            for (int r = 0; r < 4; r++) acc[mt][n][r] = 0.f;

    #pragma unroll
    for (int ks = 0; ks < 4; ks++) {
        uint32_t af[4][4];
        #pragma unroll
        for (int mt = 0; mt < 4; mt++) {
            int row = obase + mt * 16 + gp;
            int col = ks * 16 + tg * 2;
            af[mt][0] = *(const uint32_t*)&wsb[(row)     * 72 + col];
            af[mt][1] = *(const uint32_t*)&wsb[(row + 8) * 72 + col];
            af[mt][2] = *(const uint32_t*)&wsb[(row)     * 72 + col + 8];
            af[mt][3] = *(const uint32_t*)&wsb[(row + 8) * 72 + col + 8];
        }
        #pragma unroll
        for (int n = 0; n < 8; n++) {
            int nrow = n * 8 + gp, ncol = ks * 16 + tg * 2;
            uint32_t b0 = *(const uint32_t*)&ysb[nrow * 72 + ncol];
            uint32_t b1 = *(const uint32_t*)&ysb[nrow * 72 + ncol + 8];
            #pragma unroll
            for (int mt = 0; mt < 4; mt++)
                hmma(acc[mt][n], af[mt][0], af[mt][1], af[mt][2], af[mt][3], b0, b1);
        }
    }

    __nv_bfloat16* stg = wsb + w * 4608;   // [64][72]
    if (var == 2) {
        #pragma unroll
        for (int mt = 0; mt < 4; mt++)
            #pragma unroll
            for (int n = 0; n < 8; n++) {
                int d = mt * 16 + gp, lcol = n * 8 + tg * 2;
                __nv_bfloat162 h0 = __floats2bfloat162_rn(acc[mt][n][0] + pbv[mt][0],
                                                          acc[mt][n][1] + pbv[mt][0]);
                __nv_bfloat162 h1 = __floats2bfloat162_rn(acc[mt][n][2] + pbv[mt][1],
                                                          acc[mt][n][3] + pbv[mt][1]);
                *(uint32_t*)&stg[(d)     * 72 + lcol] = *(uint32_t*)&h0;
                *(uint32_t*)&stg[(d + 8) * 72 + lcol] = *(uint32_t*)&h1;
            }
    } else {
        #pragma unroll
        for (int mt = 0; mt < 4; mt++)
            #pragma unroll
            for (int n = 0; n < 8; n++) {
                int d = mt * 16 + gp, lcol = n * 8 + tg * 2;
                stg[(lcol)     * 72 + d]     = __float2bfloat16(acc[mt][n][0] + pbv[mt][0]);
                stg[(lcol + 1) * 72 + d]     = __float2bfloat16(acc[mt][n][1] + pbv[mt][0]);
                stg[(lcol)     * 72 + d + 8] = __float2bfloat16(acc[mt][n][2] + pbv[mt][1]);
                stg[(lcol + 1) * 72 + d + 8] = __float2bfloat16(acc[mt][n][3] + pbv[mt][1]);
            }
    }
    __syncwarp();

    int bh = b * CH + w;
    if (var == 2) {
        for (int i = ln; i < 512; i += 32) {
            int r = i >> 3, j = i & 7;
            *(uint4*)&g_vv[((size_t)(bh * CC + r)) * CL + l0 + j * 8] =
                *(const uint4*)&stg[r * 72 + j * 8];
        }
    } else {
        __nv_bfloat16* outp = (var == 0) ? g_qt : g_kt;
        for (int i = ln; i < 512; i += 32) {
            int r = i >> 3, j = i & 7;
            *(uint4*)&outp[((size_t)bh * CL + l0 + r) * CC + j * 8] =
                *(const uint4*)&stg[r * 72 + j * 8];
        }
    }
}

// ============================================================================
// Flash attention on HMMA. 3-buffer pipeline, 1 barrier/tile.
// Softmax: S already in log2 domain -> P = ex2.bf16x2(cvt(S)).
// Rowsum via extra HMMA against constant all-ones B fragment.
// ============================================================================
#define KT      64
#define NT      (CL / KT)
#define KV_OFF  18432
#define KV_STR  18432
#define FL_SMEM 73728

__global__ void __launch_bounds__(128, 2) flash_kernel()
{
    extern __shared__ char sm[];
    uint32_t sb = smem_u32(sm);
    __nv_bfloat16* Qsm = (__nv_bfloat16*)sm;
    float* Osm = (float*)sm;

    int tid = threadIdx.x;
    int w   = tid >> 5;
    int ln  = tid & 31;
    int gp  = ln >> 2;
    int tg  = ln & 3;
    int l0  = blockIdx.x * 128;
    int bh  = blockIdx.z * CH + blockIdx.y;

    int t4 = ln >> 3;
    uint32_t lk = (((t4 >> 1) * 8 + (ln & 7)) * 144) + ((t4 & 1) * 16);

    const __nv_bfloat16* qg = g_qt + (size_t)bh * CL * CC;
    const __nv_bfloat16* kg = g_kt + (size_t)bh * CL * CC;
    const __nv_bfloat16* vg = g_vv + (size_t)bh * CC * CL;

    for (int c = tid; c < 1024; c += 128) {
        int r = c >> 3, j = c & 7;
        cpa16(sb + r * 144 + j * 16, qg + ((size_t)(l0 + r)) * CC + j * 8);
    }
    CP_COMMIT();
    #pragma unroll
    for (int t = 0; t < 2; t++) {
        uint32_t base = sb + KV_OFF + t * KV_STR;
        int n0 = t * KT;
        for (int c = tid; c < 512; c += 128) {
            int r = c >> 3, j = c & 7;
            cpa16(base + r * 144 + j * 16, kg + ((size_t)(n0 + r)) * CC + j * 8);
            cpa16(base + 9216 + r * 144 + j * 16, vg + (size_t)r * CL + n0 + j * 8);
        }
        CP_COMMIT();
    }

    CP_WAIT(2);
    __syncthreads();
    uint32_t qa[2][4][4];
    #pragma unroll
    for (int mt = 0; mt < 2; mt++) {
        int row = w * 32 + mt * 16 + gp;
        #pragma unroll
        for (int ks = 0; ks < 4; ks++) {
            int col = ks * 16 + tg * 2;
            qa[mt][ks][0] = *(const uint32_t*)&Qsm[(row)     * 72 + col];
            qa[mt][ks][1] = *(const uint32_t*)&Qsm[(row + 8) * 72 + col];
            qa[mt][ks][2] = *(const uint32_t*)&Qsm[(row)     * 72 + col + 8];
            qa[mt][ks][3] = *(const uint32_t*)&Qsm[(row + 8) * 72 + col + 8];
        }
    }

    float Oacc[2][8][4];
    #pragma unroll
    for (int mt = 0; mt < 2; mt++)
        #pragma unroll
        for (int n = 0; n < 8; n++)
            #pragma unroll
            for (int r = 0; r < 4; r++) Oacc[mt][n][r] = 0.f;
    float Racc[2][4];
    #pragma unroll
    for (int mt = 0; mt < 2; mt++)
        #pragma unroll
        for (int r = 0; r < 4; r++) Racc[mt][r] = 0.f;

    int cur = 0, pf = 2;
    for (int i = 0; i < NT; i++) {
        if (i + 1 < NT) { CP_WAIT(1); } else { CP_WAIT(0); }
        __syncthreads();

        if (i + 2 < NT) {
            int n0 = (i + 2) * KT;
            uint32_t base = sb + KV_OFF + pf * KV_STR;
            for (int c = tid; c < 512; c += 128) {
                int r = c >> 3, j = c & 7;
                cpa16(base + r * 144 + j * 16, kg + ((size_t)(n0 + r)) * CC + j * 8);
                cpa16(base + 9216 + r * 144 + j * 16, vg + (size_t)r * CL + n0 + j * 8);
            }
            CP_COMMIT();
        }

        uint32_t kbase = sb + KV_OFF + cur * KV_STR + lk;
        uint32_t vbase = kbase + 9216;

        // ---- MMA1: S = Q . K^T (log2 domain) ----
        float Sacc[2][8][4];
        #pragma unroll
        for (int mt = 0; mt < 2; mt++)
            #pragma unroll
            for (int n = 0; n < 8; n++)
                #pragma unroll
                for (int r = 0; r < 4; r++) Sacc[mt][n][r] = 0.f;

        #pragma unroll
        for (int ks = 0; ks < 4; ks++) {
            uint32_t kb[8][2];
            #pragma unroll
            for (int ng2 = 0; ng2 < 4; ng2++)
                ldsm4(kbase + ng2 * 2304 + ks * 32,
                      kb[2 * ng2][0], kb[2 * ng2][1], kb[2 * ng2 + 1][0], kb[2 * ng2 + 1][1]);
            #pragma unroll
            for (int n = 0; n < 8; n++) {
                hmma(Sacc[0][n], qa[0][ks][0], qa[0][ks][1], qa[0][ks][2], qa[0][ks][3], kb[n][0], kb[n][1]);
                hmma(Sacc[1][n], qa[1][ks][0], qa[1][ks][1], qa[1][ks][2], qa[1][ks][3], kb[n][0], kb[n][1]);
            }
        }

        // ---- P = ex2(S) in bf16x2; O += P.V; rowsum += P.ones ----
        #pragma unroll
        for (int ks = 0; ks < 4; ks++) {
            uint32_t vb[8][2];
            #pragma unroll
            for (int ng2 = 0; ng2 < 4; ng2++)
                ldsm4(vbase + ng2 * 2304 + ks * 32,
                      vb[2 * ng2][0], vb[2 * ng2][1], vb[2 * ng2 + 1][0], vb[2 * ng2 + 1][1]);
            #pragma unroll
            for (int mt = 0; mt < 2; mt++) {
                uint32_t pa0 = ex2bf2(cvt2bf(Sacc[mt][2 * ks][1],     Sacc[mt][2 * ks][0]));
                uint32_t pa1 = ex2bf2(cvt2bf(Sacc[mt][2 * ks][3],     Sacc[mt][2 * ks][2]));
                uint32_t pa2 = ex2bf2(cvt2bf(Sacc[mt][2 * ks + 1][1], Sacc[mt][2 * ks + 1][0]));
                uint32_t pa3 = ex2bf2(cvt2bf(Sacc[mt][2 * ks + 1][3], Sacc[mt][2 * ks + 1][2]));
                #pragma unroll
                for (int n = 0; n < 8; n++)
                    hmma(Oacc[mt][n], pa0, pa1, pa2, pa3, vb[n][0], vb[n][1]);
                hmma(Racc[mt], pa0, pa1, pa2, pa3, ONESBF, ONESBF);
            }
        }

        cur = (cur == 2) ? 0 : cur + 1;
        pf  = (pf  == 2) ? 0 : pf  + 1;
    }

    float inv[2][2];
    #pragma unroll
    for (int mt = 0; mt < 2; mt++) {
        inv[mt][0] = 1.0f / Racc[mt][0];
        inv[mt][1] = 1.0f / Racc[mt][2];
    }

    __syncthreads();
    #pragma unroll
    for (int mt = 0; mt < 2; mt++) {
        int qb = w * 32 + mt * 16 + gp;
        #pragma unroll
        for (int n = 0; n < 8; n++) {
            int d = n * 8 + tg * 2;
            Osm[(d)     * 132 + qb]     = Oacc[mt][n][0] * inv[mt][0];
            Osm[(d + 1) * 132 + qb]     = Oacc[mt][n][1] * inv[mt][0];
            Osm[(d)     * 132 + qb + 8] = Oacc[mt][n][2] * inv[mt][1];
            Osm[(d + 1) * 132 + qb + 8] = Oacc[mt][n][3] * inv[mt][1];
        }
    }
    __syncthreads();

    float* ob = g_att + (size_t)bh * CC * CL + l0;
    for (int c = tid; c < 64 * 32; c += 128) {
        int d = c >> 5, q4 = (c & 31) << 2;
        *(float4*)&ob[(size_t)d * CL + q4] = *(const float4*)&Osm[d * 132 + q4];
    }
}

// ============================================================================
// Unify heads: CTA = (64-l tile, b). 3-buffer cp.async pipeline over 8 o-chunks.
// Buf j: as[64 o][68 l] fp32 then ws[64 c][68 o'] fp32 (loaded in natural layouts).
// ============================================================================
#define UB_STR  34816
#define U_SMEM  (3 * UB_STR)

__global__ void __launch_bounds__(256, 1) unify_kernel(
    const float* __restrict__ uw, const float* __restrict__ ub,
    float* __restrict__ y)
{
    extern __shared__ float usm[];
    uint32_t sbU = smem_u32(usm);

    int tid = threadIdx.x;
    int tx = tid & 15, ty = tid >> 4;
    int l0 = blockIdx.x * 64, b = blockIdx.y;

    // issue tile t into buf t%3
    auto issue = [&](int t) {
        uint32_t base = sbU + (t % 3) * UB_STR;
        const float* ag = g_att + (size_t)(b * CO + t * 64) * CL + l0;
        for (int i = tid; i < 1024; i += 256) {
            int o = i >> 4, j = i & 15;
            cpa16(base + o * 272 + j * 16, ag + (size_t)o * CL + j * 4);
        }
        const float* wg = uw + t * 64;
        for (int i = tid; i < 1024; i += 256) {
            int c = i >> 4, j = i & 15;
            cpa16(base + 17408 + c * 272 + j * 16, wg + (size_t)c * CO + j * 4);
        }
        CP_COMMIT();
    };

    issue(0);
    issue(1);

    ull acc[4][2];
    #pragma unroll
    for (int i = 0; i < 4; i++) { acc[i][0] = 0ull; acc[i][1] = 0ull; }

    for (int oc = 0; oc < 8; oc++) {
        if (oc < 7) { CP_WAIT(1); } else { CP_WAIT(0); }
        __syncthreads();
        if (oc + 2 < 8) issue(oc + 2);   // buf (oc+2)%3 == (oc-1)%3: free

        const float* as_ = usm + (oc % 3) * (UB_STR / 4);
        const float* ws  = as_ + 4352;   // 17408 B / 4

        #pragma unroll 2
        for (int os = 0; os < 64; os += 4) {
            ull a01[4], a23[4];
            #pragma unroll
            for (int oo = 0; oo < 4; oo++) {
                float4 av = *(const float4*)&as_[(os + oo) * 68 + tx * 4];
                a01[oo] = f2pack(av.x, av.y);
                a23[oo] = f2pack(av.z, av.w);
            }
            #pragma unroll
            for (int cc = 0; cc < 4; cc++) {
                float4 wv = *(const float4*)&ws[(ty * 4 + cc) * 68 + os];
                ull w0 = f2pack(wv.x, wv.x), w1 = f2pack(wv.y, wv.y);
                ull w2 = f2pack(wv.z, wv.z), w3 = f2pack(wv.w, wv.w);
                acc[cc][0] = f2fma(w0, a01[0], acc[cc][0]);
                acc[cc][1] = f2fma(w0, a23[0], acc[cc][1]);
                acc[cc][0] = f2fma(w1, a01[1], acc[cc][0]);
                acc[cc][1] = f2fma(w1, a23[1], acc[cc][1]);
                acc[cc][0] = f2fma(w2, a01[2], acc[cc][0]);
                acc[cc][1] = f2fma(w2, a23[2], acc[cc][1]);
                acc[cc][0] = f2fma(w3, a01[3], acc[cc][0]);
                acc[cc][1] = f2fma(w3, a23[3], acc[cc][1]);
            }
        }
    }

    #pragma unroll
    for (int cc = 0; cc < 4; cc++) {
        int c = ty * 4 + cc;
        float bb = ub[c];
        float a0, a1, a2, a3;
        f2unpack(acc[cc][0], a0, a1);
        f2unpack(acc[cc][1], a2, a3);
        float4 r = make_float4(a0 + bb, a1 + bb, a2 + bb, a3 + bb);
        *(float4*)&y[(size_t)(b * CC + c) * CL + l0 + tx * 4] = r;
    }
}

// ============================================================================
extern "C" void kernel_launch(void* const* d_in, const int* in_sizes, int n_in,
                              void* d_out, int out_size)
{
    (void)in_sizes; (void)n_in; (void)out_size;
    const float* x    = (const float*)d_in[0];
    const float* q_dw = (const float*)d_in[1];
    const float* q_db = (const float*)d_in[2];
    const float* q_pw = (const float*)d_in[3];
    const float* q_pb = (const float*)d_in[4];
    const float* k_dw = (const float*)d_in[5];
    const float* k_db = (const float*)d_in[6];
    const float* k_pw = (const float*)d_in[7];
    const float* k_pb = (const float*)d_in[8];
    const float* v_dw = (const float*)d_in[9];
    const float* v_db = (const float*)d_in[10];
    const float* v_pw = (const float*)d_in[11];
    const float* v_pb = (const float*)d_in[12];
    const float* u_w  = (const float*)d_in[13];
    const float* u_b  = (const float*)d_in[14];

    cudaFuncSetAttribute(qkv_kernel,
                         cudaFuncAttributeMaxDynamicSharedMemorySize, QKV_SMEM);
    cudaFuncSetAttribute(flash_kernel,
                         cudaFuncAttributeMaxDynamicSharedMemorySize, FL_SMEM);
    cudaFuncSetAttribute(unify_kernel,
                         cudaFuncAttributeMaxDynamicSharedMemorySize, U_SMEM);

    prep_kernel<<<96, 256>>>(q_pw, k_pw, v_pw);

    qkv_kernel<<<dim3(CL / 64, CB, 3), 256, QKV_SMEM>>>(
        x, q_dw, q_db, q_pb, k_dw, k_db, k_pb, v_dw, v_db, v_pb);

    flash_kernel<<<dim3(CL / 128, CH, CB), 128, FL_SMEM>>>();

    unify_kernel<<<dim3(CL / 64, CB), 256, U_SMEM>>>(u_w, u_b, (float*)d_out);
}

// round 7
// speedup vs baseline: 7.4855x; 1.0490x over previous
#include <cuda_runtime.h>
#include <cuda_bf16.h>
#include <cstdint>

#define CB 4
#define CC 64
#define CH 8
#define CL 2048
#define CO 512

#define QK_SCALE 0.35355339059327373f
#define LOG2E    1.4426950408889634f

typedef unsigned long long ull;

// ---------------- packed f32x2 helpers ----------------
__device__ __forceinline__ ull f2pack(float lo, float hi) {
    ull d; asm("mov.b64 %0, {%1, %2};" : "=l"(d) : "f"(lo), "f"(hi)); return d;
}
__device__ __forceinline__ void f2unpack(ull v, float& lo, float& hi) {
    asm("mov.b64 {%0, %1}, %2;" : "=f"(lo), "=f"(hi) : "l"(v));
}

// ---------------- bf16x2 exp2 path ----------------
__device__ __forceinline__ uint32_t cvt2bf(float hi, float lo) {
    uint32_t d; asm("cvt.rn.bf16x2.f32 %0, %1, %2;" : "=r"(d) : "f"(hi), "f"(lo)); return d;
}
__device__ __forceinline__ uint32_t ex2bf2(uint32_t x) {
    uint32_t d; asm("ex2.approx.ftz.bf16x2 %0, %1;" : "=r"(d) : "r"(x)); return d;
}
#define ONESBF 0x3F803F80u

// ---------------- cp.async ----------------
__device__ __forceinline__ void cpa16(uint32_t s, const void* g) {
    asm volatile("cp.async.cg.shared.global [%0], [%1], 16;" :: "r"(s), "l"(g));
}
#define CP_COMMIT() asm volatile("cp.async.commit_group;" ::: "memory")
#define CP_WAIT(n)  asm volatile("cp.async.wait_group %0;" :: "n"(n) : "memory")

__device__ __forceinline__ uint32_t smem_u32(const void* p) {
    uint32_t a;
    asm("{ .reg .u64 t; cvta.to.shared.u64 t, %1; cvt.u32.u64 %0, t; }" : "=r"(a) : "l"(p));
    return a;
}

// ---------------- HMMA m16n8k16 bf16 ----------------
__device__ __forceinline__ void hmma(float* c,
                                     uint32_t a0, uint32_t a1, uint32_t a2, uint32_t a3,
                                     uint32_t b0, uint32_t b1) {
    asm volatile(
        "mma.sync.aligned.m16n8k16.row.col.f32.bf16.bf16.f32 "
        "{%0,%1,%2,%3},{%4,%5,%6,%7},{%8,%9},{%0,%1,%2,%3};"
        : "+f"(c[0]), "+f"(c[1]), "+f"(c[2]), "+f"(c[3])
        : "r"(a0), "r"(a1), "r"(a2), "r"(a3), "r"(b0), "r"(b1));
}

// ---------------- HMMA m16n8k8 tf32 (fp32 bits truncated by HW) ----------------
__device__ __forceinline__ void tmma(float* c,
                                     uint32_t a0, uint32_t a1, uint32_t a2, uint32_t a3,
                                     uint32_t b0, uint32_t b1) {
    asm volatile(
        "mma.sync.aligned.m16n8k8.row.col.f32.tf32.tf32.f32 "
        "{%0,%1,%2,%3},{%4,%5,%6,%7},{%8,%9},{%0,%1,%2,%3};"
        : "+f"(c[0]), "+f"(c[1]), "+f"(c[2]), "+f"(c[3])
        : "r"(a0), "r"(a1), "r"(a2), "r"(a3), "r"(b0), "r"(b1));
}

__device__ __forceinline__ void ldsm4(uint32_t a, uint32_t& r0, uint32_t& r1,
                                      uint32_t& r2, uint32_t& r3) {
    asm volatile("ldmatrix.sync.aligned.m8n8.x4.shared.b16 {%0,%1,%2,%3}, [%4];"
        : "=r"(r0), "=r"(r1), "=r"(r2), "=r"(r3) : "r"(a));
}

// ---------------- scratch ----------------
__device__ __nv_bfloat16 g_qt[CB * CH * CL * CC];   // [bh][l][c]  (q prescaled)
__device__ __nv_bfloat16 g_kt[CB * CH * CL * CC];   // [bh][l][c]
__device__ __nv_bfloat16 g_vv[CB * CH * CC * CL];   // [bh][d][l]
__device__ float g_att[CB * CO * CL];               // [(b*512 + h*64 + d)][l]
__device__ __nv_bfloat16 g_w[3 * CO * CC];          // preconverted pw (scales folded)

// ============================================================================
// Prep: convert pointwise weights fp32 -> bf16; fold C^-0.25 (and log2e for q).
// ============================================================================
__global__ __launch_bounds__(256) void prep_kernel(
    const float* __restrict__ qpw, const float* __restrict__ kpw,
    const float* __restrict__ vpw)
{
    int i = blockIdx.x * 256 + threadIdx.x;
    int var = i / 8192;
    int off = (i - var * 8192) * 4;
    const float* src = (var == 0) ? qpw : (var == 1) ? kpw : vpw;
    float s = (var == 0) ? QK_SCALE * LOG2E : (var == 1) ? QK_SCALE : 1.0f;
    float4 wv = *(const float4*)&src[off];
    __nv_bfloat162 h0 = __floats2bfloat162_rn(wv.x * s, wv.y * s);
    __nv_bfloat162 h1 = __floats2bfloat162_rn(wv.z * s, wv.w * s);
    *(uint2*)&g_w[var * (CO * CC) + off] = make_uint2(*(uint32_t*)&h0, *(uint32_t*)&h1);
}

// ============================================================================
// QKV on HMMA. CTA = (64-seq tile, b, variant). 8 warps; warp w owns head w.
// ============================================================================
#define QKV_SMEM 82944

__global__ void __launch_bounds__(256) qkv_kernel(
    const float* __restrict__ x,
    const float* __restrict__ qdw, const float* __restrict__ qdb,
    const float* __restrict__ qpb,
    const float* __restrict__ kdw, const float* __restrict__ kdb,
    const float* __restrict__ kpb,
    const float* __restrict__ vdw, const float* __restrict__ vdb,
    const float* __restrict__ vpb)
{
    extern __shared__ char qsm[];
    __nv_bfloat16* ysb = (__nv_bfloat16*)qsm;            // [64 l][72 c]
    __nv_bfloat16* wsb = (__nv_bfloat16*)(qsm + 9216);   // [512 o][72 c]
    uint32_t sb = smem_u32(qsm);

    int var = blockIdx.z;
    const float* dw = (var == 0) ? qdw : (var == 1) ? kdw : vdw;
    const float* db = (var == 0) ? qdb : (var == 1) ? kdb : vdb;
    const float* pb = (var == 0) ? qpb : (var == 1) ? kpb : vpb;
    float bscale   = (var == 0) ? QK_SCALE * LOG2E : (var == 1) ? QK_SCALE : 1.0f;

    int l0 = blockIdx.x * 64;
    int b  = blockIdx.y;
    int tid = threadIdx.x;
    int w = tid >> 5, ln = tid & 31, gp = ln >> 2, tg = ln & 3;

    const __nv_bfloat16* wg = g_w + (size_t)var * (CO * CC);
    for (int i = tid; i < 4096; i += 256) {
        int r = i >> 3, j = i & 7;
        cpa16(sb + 9216 + r * 144 + j * 16, wg + (size_t)r * CC + j * 8);
    }
    CP_COMMIT();

    for (int idx = tid; idx < 64 * 64; idx += 256) {
        int c = idx >> 6, li = idx & 63;
        int l = l0 + li;
        const float* xr = x + (size_t)(b * CC + c) * CL;
        float w0 = dw[c * 3 + 0], w1 = dw[c * 3 + 1], w2 = dw[c * 3 + 2];
        float xm = (l > 0)      ? xr[l - 1] : 0.f;
        float x0 = xr[l];
        float xp = (l < CL - 1) ? xr[l + 1] : 0.f;
        ysb[li * 72 + c] = __float2bfloat16(db[c] + w0 * xm + w1 * x0 + w2 * xp);
    }
    CP_WAIT(0);
    __syncthreads();

    int obase = w * 64;
    float pbv[4][2];
    #pragma unroll
    for (int mt = 0; mt < 4; mt++) {
        pbv[mt][0] = pb[obase + mt * 16 + gp] * bscale;
        pbv[mt][1] = pb[obase + mt * 16 + gp + 8] * bscale;
    }

    float acc[4][8][4];
    #pragma unroll
    for (int mt = 0; mt < 4; mt++)
        #pragma unroll
        for (int n = 0; n < 8; n++)
            #pragma unroll
            for (int r = 0; r < 4; r++) acc[mt][n][r] = 0.f;

    #pragma unroll
    for (int ks = 0; ks < 4; ks++) {
        uint32_t af[4][4];
        #pragma unroll
        for (int mt = 0; mt < 4; mt++) {
            int row = obase + mt * 16 + gp;
            int col = ks * 16 + tg * 2;
            af[mt][0] = *(const uint32_t*)&wsb[(row)     * 72 + col];
            af[mt][1] = *(const uint32_t*)&wsb[(row + 8) * 72 + col];
            af[mt][2] = *(const uint32_t*)&wsb[(row)     * 72 + col + 8];
            af[mt][3] = *(const uint32_t*)&wsb[(row + 8) * 72 + col + 8];
        }
        #pragma unroll
        for (int n = 0; n < 8; n++) {
            int nrow = n * 8 + gp, ncol = ks * 16 + tg * 2;
            uint32_t b0 = *(const uint32_t*)&ysb[nrow * 72 + ncol];
            uint32_t b1 = *(const uint32_t*)&ysb[nrow * 72 + ncol + 8];
            #pragma unroll
            for (int mt = 0; mt < 4; mt++)
                hmma(acc[mt][n], af[mt][0], af[mt][1], af[mt][2], af[mt][3], b0, b1);
        }
    }

    __nv_bfloat16* stg = wsb + w * 4608;   // [64][72]
    if (var == 2) {
        #pragma unroll
        for (int mt = 0; mt < 4; mt++)
            #pragma unroll
            for (int n = 0; n < 8; n++) {
                int d = mt * 16 + gp, lcol = n * 8 + tg * 2;
                __nv_bfloat162 h0 = __floats2bfloat162_rn(acc[mt][n][0] + pbv[mt][0],
                                                          acc[mt][n][1] + pbv[mt][0]);
                __nv_bfloat162 h1 = __floats2bfloat162_rn(acc[mt][n][2] + pbv[mt][1],
                                                          acc[mt][n][3] + pbv[mt][1]);
                *(uint32_t*)&stg[(d)     * 72 + lcol] = *(uint32_t*)&h0;
                *(uint32_t*)&stg[(d + 8) * 72 + lcol] = *(uint32_t*)&h1;
            }
    } else {
        #pragma unroll
        for (int mt = 0; mt < 4; mt++)
            #pragma unroll
            for (int n = 0; n < 8; n++) {
                int d = mt * 16 + gp, lcol = n * 8 + tg * 2;
                stg[(lcol)     * 72 + d]     = __float2bfloat16(acc[mt][n][0] + pbv[mt][0]);
                stg[(lcol + 1) * 72 + d]     = __float2bfloat16(acc[mt][n][1] + pbv[mt][0]);
                stg[(lcol)     * 72 + d + 8] = __float2bfloat16(acc[mt][n][2] + pbv[mt][1]);
                stg[(lcol + 1) * 72 + d + 8] = __float2bfloat16(acc[mt][n][3] + pbv[mt][1]);
            }
    }
    __syncwarp();

    int bh = b * CH + w;
    if (var == 2) {
        for (int i = ln; i < 512; i += 32) {
            int r = i >> 3, j = i & 7;
            *(uint4*)&g_vv[((size_t)(bh * CC + r)) * CL + l0 + j * 8] =
                *(const uint4*)&stg[r * 72 + j * 8];
        }
    } else {
        __nv_bfloat16* outp = (var == 0) ? g_qt : g_kt;
        for (int i = ln; i < 512; i += 32) {
            int r = i >> 3, j = i & 7;
            *(uint4*)&outp[((size_t)bh * CL + l0 + r) * CC + j * 8] =
                *(const uint4*)&stg[r * 72 + j * 8];
        }
    }
}

// ============================================================================
// Flash attention on HMMA. 3-buffer pipeline, 1 barrier/tile.
// ============================================================================
#define KT      64
#define NT      (CL / KT)
#define KV_OFF  18432
#define KV_STR  18432
#define FL_SMEM 73728

__global__ void __launch_bounds__(128, 2) flash_kernel()
{
    extern __shared__ char sm[];
    uint32_t sb = smem_u32(sm);
    __nv_bfloat16* Qsm = (__nv_bfloat16*)sm;
    float* Osm = (float*)sm;

    int tid = threadIdx.x;
    int w   = tid >> 5;
    int ln  = tid & 31;
    int gp  = ln >> 2;
    int tg  = ln & 3;
    int l0  = blockIdx.x * 128;
    int bh  = blockIdx.z * CH + blockIdx.y;

    int t4 = ln >> 3;
    uint32_t lk = (((t4 >> 1) * 8 + (ln & 7)) * 144) + ((t4 & 1) * 16);

    const __nv_bfloat16* qg = g_qt + (size_t)bh * CL * CC;
    const __nv_bfloat16* kg = g_kt + (size_t)bh * CL * CC;
    const __nv_bfloat16* vg = g_vv + (size_t)bh * CC * CL;

    for (int c = tid; c < 1024; c += 128) {
        int r = c >> 3, j = c & 7;
        cpa16(sb + r * 144 + j * 16, qg + ((size_t)(l0 + r)) * CC + j * 8);
    }
    CP_COMMIT();
    #pragma unroll
    for (int t = 0; t < 2; t++) {
        uint32_t base = sb + KV_OFF + t * KV_STR;
        int n0 = t * KT;
        for (int c = tid; c < 512; c += 128) {
            int r = c >> 3, j = c & 7;
            cpa16(base + r * 144 + j * 16, kg + ((size_t)(n0 + r)) * CC + j * 8);
            cpa16(base + 9216 + r * 144 + j * 16, vg + (size_t)r * CL + n0 + j * 8);
        }
        CP_COMMIT();
    }

    CP_WAIT(2);
    __syncthreads();
    uint32_t qa[2][4][4];
    #pragma unroll
    for (int mt = 0; mt < 2; mt++) {
        int row = w * 32 + mt * 16 + gp;
        #pragma unroll
        for (int ks = 0; ks < 4; ks++) {
            int col = ks * 16 + tg * 2;
            qa[mt][ks][0] = *(const uint32_t*)&Qsm[(row)     * 72 + col];
            qa[mt][ks][1] = *(const uint32_t*)&Qsm[(row + 8) * 72 + col];
            qa[mt][ks][2] = *(const uint32_t*)&Qsm[(row)     * 72 + col + 8];
            qa[mt][ks][3] = *(const uint32_t*)&Qsm[(row + 8) * 72 + col + 8];
        }
    }

    float Oacc[2][8][4];
    #pragma unroll
    for (int mt = 0; mt < 2; mt++)
        #pragma unroll
        for (int n = 0; n < 8; n++)
            #pragma unroll
            for (int r = 0; r < 4; r++) Oacc[mt][n][r] = 0.f;
    float Racc[2][4];
    #pragma unroll
    for (int mt = 0; mt < 2; mt++)
        #pragma unroll
        for (int r = 0; r < 4; r++) Racc[mt][r] = 0.f;

    int cur = 0, pf = 2;
    for (int i = 0; i < NT; i++) {
        if (i + 1 < NT) { CP_WAIT(1); } else { CP_WAIT(0); }
        __syncthreads();

        if (i + 2 < NT) {
            int n0 = (i + 2) * KT;
            uint32_t base = sb + KV_OFF + pf * KV_STR;
            for (int c = tid; c < 512; c += 128) {
                int r = c >> 3, j = c & 7;
                cpa16(base + r * 144 + j * 16, kg + ((size_t)(n0 + r)) * CC + j * 8);
                cpa16(base + 9216 + r * 144 + j * 16, vg + (size_t)r * CL + n0 + j * 8);
            }
            CP_COMMIT();
        }

        uint32_t kbase = sb + KV_OFF + cur * KV_STR + lk;
        uint32_t vbase = kbase + 9216;

        float Sacc[2][8][4];
        #pragma unroll
        for (int mt = 0; mt < 2; mt++)
            #pragma unroll
            for (int n = 0; n < 8; n++)
                #pragma unroll
                for (int r = 0; r < 4; r++) Sacc[mt][n][r] = 0.f;

        #pragma unroll
        for (int ks = 0; ks < 4; ks++) {
            uint32_t kb[8][2];
            #pragma unroll
            for (int ng2 = 0; ng2 < 4; ng2++)
                ldsm4(kbase + ng2 * 2304 + ks * 32,
                      kb[2 * ng2][0], kb[2 * ng2][1], kb[2 * ng2 + 1][0], kb[2 * ng2 + 1][1]);
            #pragma unroll
            for (int n = 0; n < 8; n++) {
                hmma(Sacc[0][n], qa[0][ks][0], qa[0][ks][1], qa[0][ks][2], qa[0][ks][3], kb[n][0], kb[n][1]);
                hmma(Sacc[1][n], qa[1][ks][0], qa[1][ks][1], qa[1][ks][2], qa[1][ks][3], kb[n][0], kb[n][1]);
            }
        }

        #pragma unroll
        for (int ks = 0; ks < 4; ks++) {
            uint32_t vb[8][2];
            #pragma unroll
            for (int ng2 = 0; ng2 < 4; ng2++)
                ldsm4(vbase + ng2 * 2304 + ks * 32,
                      vb[2 * ng2][0], vb[2 * ng2][1], vb[2 * ng2 + 1][0], vb[2 * ng2 + 1][1]);
            #pragma unroll
            for (int mt = 0; mt < 2; mt++) {
                uint32_t pa0 = ex2bf2(cvt2bf(Sacc[mt][2 * ks][1],     Sacc[mt][2 * ks][0]));
                uint32_t pa1 = ex2bf2(cvt2bf(Sacc[mt][2 * ks][3],     Sacc[mt][2 * ks][2]));
                uint32_t pa2 = ex2bf2(cvt2bf(Sacc[mt][2 * ks + 1][1], Sacc[mt][2 * ks + 1][0]));
                uint32_t pa3 = ex2bf2(cvt2bf(Sacc[mt][2 * ks + 1][3], Sacc[mt][2 * ks + 1][2]));
                #pragma unroll
                for (int n = 0; n < 8; n++)
                    hmma(Oacc[mt][n], pa0, pa1, pa2, pa3, vb[n][0], vb[n][1]);
                hmma(Racc[mt], pa0, pa1, pa2, pa3, ONESBF, ONESBF);
            }
        }

        cur = (cur == 2) ? 0 : cur + 1;
        pf  = (pf  == 2) ? 0 : pf  + 1;
    }

    float inv[2][2];
    #pragma unroll
    for (int mt = 0; mt < 2; mt++) {
        inv[mt][0] = 1.0f / Racc[mt][0];
        inv[mt][1] = 1.0f / Racc[mt][2];
    }

    __syncthreads();
    #pragma unroll
    for (int mt = 0; mt < 2; mt++) {
        int qb = w * 32 + mt * 16 + gp;
        #pragma unroll
        for (int n = 0; n < 8; n++) {
            int d = n * 8 + tg * 2;
            Osm[(d)     * 132 + qb]     = Oacc[mt][n][0] * inv[mt][0];
            Osm[(d + 1) * 132 + qb]     = Oacc[mt][n][1] * inv[mt][0];
            Osm[(d)     * 132 + qb + 8] = Oacc[mt][n][2] * inv[mt][1];
            Osm[(d + 1) * 132 + qb + 8] = Oacc[mt][n][3] * inv[mt][1];
        }
    }
    __syncthreads();

    float* ob = g_att + (size_t)bh * CC * CL + l0;
    for (int c = tid; c < 64 * 32; c += 128) {
        int d = c >> 5, q4 = (c & 31) << 2;
        *(float4*)&ob[(size_t)d * CL + q4] = *(const float4*)&Osm[d * 132 + q4];
    }
}

// ============================================================================
// Unify heads on tf32 HMMA. CTA = (64-l tile, b); y[c][l] = W[c][o] x att[o][l].
// 8 warps: wm = w&3 -> 16 c rows; wn = w>>2 -> 32 l cols. K = 512 in 8 chunks.
// Buf: att [64 o][68 l] fp32 @0, W [64 c][68 o] fp32 @17408B. 3-buf cp.async.
// fp32 bits fed to tf32 mma directly (HW truncates: rel ~4e-5/term, negligible).
// ============================================================================
#define UB_STR  34816
#define U_SMEM  (3 * UB_STR)

__global__ void __launch_bounds__(256, 1) unify_kernel(
    const float* __restrict__ uw, const float* __restrict__ ub,
    float* __restrict__ y)
{
    extern __shared__ float usm[];
    uint32_t sbU = smem_u32(usm);

    int tid = threadIdx.x;
    int w = tid >> 5, ln = tid & 31, gp = ln >> 2, tg = ln & 3;
    int wm = w & 3, wn = w >> 2;
    int l0 = blockIdx.x * 64, b = blockIdx.y;

    auto issue = [&](int t) {
        uint32_t base = sbU + (t % 3) * UB_STR;
        const float* ag = g_att + (size_t)(b * CO + t * 64) * CL + l0;
        for (int i = tid; i < 1024; i += 256) {
            int o = i >> 4, j = i & 15;
            cpa16(base + o * 272 + j * 16, ag + (size_t)o * CL + j * 4);
        }
        const float* wg = uw + t * 64;
        for (int i = tid; i < 1024; i += 256) {
            int c = i >> 4, j = i & 15;
            cpa16(base + 17408 + c * 272 + j * 16, wg + (size_t)c * CO + j * 4);
        }
        CP_COMMIT();
    };

    issue(0);
    issue(1);

    float acc[4][4];   // [n-subtile][frag]
    #pragma unroll
    for (int ns = 0; ns < 4; ns++)
        #pragma unroll
        for (int r = 0; r < 4; r++) acc[ns][r] = 0.f;

    for (int t = 0; t < 8; t++) {
        if (t < 7) { CP_WAIT(1); } else { CP_WAIT(0); }
        __syncthreads();
        if (t + 2 < 8) issue(t + 2);

        const float* Batt = usm + (t % 3) * (UB_STR / 4);   // [o][68 l]
        const float* Aw   = Batt + 4352;                    // [c][68 o]

        #pragma unroll
        for (int ks = 0; ks < 8; ks++) {
            int k0 = ks * 8;
            int ra = (wm * 16 + gp) * 68 + k0;
            uint32_t a0 = *(const uint32_t*)&Aw[ra + tg];
            uint32_t a1 = *(const uint32_t*)&Aw[ra + 8 * 68 + tg];
            uint32_t a2 = *(const uint32_t*)&Aw[ra + tg + 4];
            uint32_t a3 = *(const uint32_t*)&Aw[ra + 8 * 68 + tg + 4];
            int rb0 = (k0 + tg) * 68 + wn * 32 + gp;
            int rb1 = (k0 + tg + 4) * 68 + wn * 32 + gp;
            #pragma unroll
            for (int ns = 0; ns < 4; ns++) {
                uint32_t b0 = *(const uint32_t*)&Batt[rb0 + ns * 8];
                uint32_t b1 = *(const uint32_t*)&Batt[rb1 + ns * 8];
                tmma(acc[ns], a0, a1, a2, a3, b0, b1);
            }
        }
    }

    // stage y tile [64 c][68 l] into buf 0, then coalesced float4 stores
    __syncthreads();
    float* stg = usm;
    #pragma unroll
    for (int ns = 0; ns < 4; ns++) {
        int lcol = wn * 32 + ns * 8 + tg * 2;
        int c = wm * 16 + gp;
        *(float2*)&stg[(c)     * 68 + lcol] = make_float2(acc[ns][0], acc[ns][1]);
        *(float2*)&stg[(c + 8) * 68 + lcol] = make_float2(acc[ns][2], acc[ns][3]);
    }
    __syncthreads();

    for (int i = tid; i < 1024; i += 256) {
        int c = i >> 4, l4 = (i & 15) << 2;
        float bb = ub[c];
        float4 v = *(const float4*)&stg[c * 68 + l4];
        v.x += bb; v.y += bb; v.z += bb; v.w += bb;
        *(float4*)&y[(size_t)(b * CC + c) * CL + l0 + l4] = v;
    }
}

// ============================================================================
extern "C" void kernel_launch(void* const* d_in, const int* in_sizes, int n_in,
                              void* d_out, int out_size)
{
    (void)in_sizes; (void)n_in; (void)out_size;
    const float* x    = (const float*)d_in[0];
    const float* q_dw = (const float*)d_in[1];
    const float* q_db = (const float*)d_in[2];
    const float* q_pw = (const float*)d_in[3];
    const float* q_pb = (const float*)d_in[4];
    const float* k_dw = (const float*)d_in[5];
    const float* k_db = (const float*)d_in[6];
    const float* k_pw = (const float*)d_in[7];
    const float* k_pb = (const float*)d_in[8];
    const float* v_dw = (const float*)d_in[9];
    const float* v_db = (const float*)d_in[10];
    const float* v_pw = (const float*)d_in[11];
    const float* v_pb = (const float*)d_in[12];
    const float* u_w  = (const float*)d_in[13];
    const float* u_b  = (const float*)d_in[14];

    cudaFuncSetAttribute(qkv_kernel,
                         cudaFuncAttributeMaxDynamicSharedMemorySize, QKV_SMEM);
    cudaFuncSetAttribute(flash_kernel,
                         cudaFuncAttributeMaxDynamicSharedMemorySize, FL_SMEM);
    cudaFuncSetAttribute(unify_kernel,
                         cudaFuncAttributeMaxDynamicSharedMemorySize, U_SMEM);

    prep_kernel<<<96, 256>>>(q_pw, k_pw, v_pw);

    qkv_kernel<<<dim3(CL / 64, CB, 3), 256, QKV_SMEM>>>(
        x, q_dw, q_db, q_pb, k_dw, k_db, k_pb, v_dw, v_db, v_pb);

    flash_kernel<<<dim3(CL / 128, CH, CB), 128, FL_SMEM>>>();

    unify_kernel<<<dim3(CL / 64, CB), 256, U_SMEM>>>(u_w, u_b, (float*)d_out);
}